// round 13
// baseline (speedup 1.0000x reference)
#include <cuda_runtime.h>
#include <cuda_fp16.h>
#include <stdint.h>

#define BSZ 2
#define SEQ 2048
#define DIMM 1024
#define CCH 1024
#define NHH 16
#define HDD 64
#define MROWS (BSZ*SEQ)   // 4096

// ---------------- fp16 scratch (device globals) ----------------------------------
__device__ __half g_xh [MROWS*DIMM];
__device__ __half g_xlo[MROWS*DIMM];
__device__ __half g_w16[7][DIMM*CCH];          // wq,wk,wv,qpw,kpw,vpw,wo
__device__ float  g_dwt[3*3*CCH];              // transposed dw weights [qkv][tap][C]
__device__ __half g_q16[MROWS*CCH],  g_k16[MROWS*CCH];
__device__ __half g_vhi[MROWS*CCH],  g_vlo[MROWS*CCH];
__device__ __half g_qc16[MROWS*CCH], g_kc16[MROWS*CCH];
__device__ __half g_vchi[MROWS*CCH], g_vclo[MROWS*CCH];
__device__ __half g_qpw[MROWS*CCH],  g_kpw[MROWS*CCH], g_vpw[MROWS*CCH];
__device__ __half g_qn[MROWS*CCH],   g_kn[MROWS*CCH],  g_vt[MROWS*CCH];
__device__ __half g_aoh[MROWS*CCH],  g_aol[MROWS*CCH];

// ================= helpers =======================================================
__device__ __forceinline__ uint32_t smem_u32(const void* p) {
    uint32_t a;
    asm("{ .reg .u64 t; cvta.to.shared.u64 t, %1; cvt.u32.u64 %0, t; }" : "=r"(a) : "l"(p));
    return a;
}
__device__ __forceinline__ uint32_t pack2f16(float x, float y) {
    __half2 t = __floats2half2_rn(x, y);
    return *reinterpret_cast<uint32_t*>(&t);
}
__device__ __forceinline__ void split2h(float x, float y, uint32_t& h, uint32_t& l) {
    __half hx = __float2half_rn(x);
    __half hy = __float2half_rn(y);
    __half2 hp = __halves2half2(hx, hy);
    h = *reinterpret_cast<uint32_t*>(&hp);
    l = pack2f16(x - __half2float(hx), y - __half2float(hy));
}
__device__ __forceinline__ void mma_f16(float* d, const uint32_t* a, const uint32_t* b) {
    asm volatile(
        "mma.sync.aligned.m16n8k16.row.col.f32.f16.f16.f32 "
        "{%0,%1,%2,%3}, {%4,%5,%6,%7}, {%8,%9}, {%0,%1,%2,%3};"
        : "+f"(d[0]), "+f"(d[1]), "+f"(d[2]), "+f"(d[3])
        : "r"(a[0]), "r"(a[1]), "r"(a[2]), "r"(a[3]), "r"(b[0]), "r"(b[1]));
}
__device__ __forceinline__ void mma_f16_b(float* d, const uint32_t* a, uint32_t b0, uint32_t b1) {
    asm volatile(
        "mma.sync.aligned.m16n8k16.row.col.f32.f16.f16.f32 "
        "{%0,%1,%2,%3}, {%4,%5,%6,%7}, {%8,%9}, {%0,%1,%2,%3};"
        : "+f"(d[0]), "+f"(d[1]), "+f"(d[2]), "+f"(d[3])
        : "r"(a[0]), "r"(a[1]), "r"(a[2]), "r"(a[3]), "r"(b0), "r"(b1));
}
__device__ __forceinline__ void ldm_x4(uint32_t& r0, uint32_t& r1, uint32_t& r2, uint32_t& r3,
                                       uint32_t addr) {
    asm volatile("ldmatrix.sync.aligned.m8n8.x4.shared.b16 {%0,%1,%2,%3}, [%4];"
                 : "=r"(r0), "=r"(r1), "=r"(r2), "=r"(r3) : "r"(addr));
}
__device__ __forceinline__ float exp_small(float x) {   // |x| <= 0.125, rel err ~3e-8
    return 1.f + x * (1.f + x * (0.5f + x * (0.166666667f + x * 0.0416666667f)));
}

// ================= prep kernels ==================================================
struct WC { const float* s[7]; __half* d[7]; const float* dw[3]; float* dwt; };
__global__ void wconv_k(WC wc)
{
    int z = blockIdx.y;
    int i = blockIdx.x * 256 + threadIdx.x;
    if (z < 7) {
        const float2* s = (const float2*)wc.s[z];
        __half2* d = (__half2*)wc.d[z];
        float2 v = s[i];
        d[i] = __floats2half2_rn(v.x, v.y);
    } else {
        if (i < 3 * 3 * CCH) {
            int plane = i / (3 * CCH);
            int r = i % (3 * CCH);
            int tap = r >> 10, c = r & (CCH - 1);
            wc.dwt[plane * 3 * CCH + tap * CCH + c] = wc.dw[plane][c * 3 + tap];
        }
    }
}
__global__ void xconv_k(const float2* x, uint32_t* xh, uint32_t* xl)
{
    int i = blockIdx.x * 256 + threadIdx.x;    // < 2M
    float2 v = x[i];
    uint32_t h, l;
    split2h(v.x, v.y, h, l);
    xh[i] = h; xl[i] = l;
}

// ================= fp16 GEMM: cp.async + ldmatrix + mma ==========================
struct GH { const __half* A; const __half* Al; const __half* W; const float* bias;
            void* C; void* Cl; int prod; int omode; };

#define PL_A 5120
#define PL_B 10240
#define G_STB (2*PL_A + PL_B)
#define G_NST 3
#define G_SMEM (G_NST*G_STB)         // 61440

template<bool SILU>
__global__ void __launch_bounds__(256, 3)
gemm_h_k(GH g0, GH g1, GH g2)
{
    GH g = (blockIdx.z == 0) ? g0 : ((blockIdx.z == 1) ? g1 : g2);
    const int prod = g.prod;
    extern __shared__ uint32_t smw[];
    const uint32_t sb = smem_u32(smw);

    const int tid = threadIdx.x, lane = tid & 31, wid = tid >> 5;
    const int wm = wid & 1, wn = wid >> 1;
    const int gr = lane >> 2, gc = lane & 3;
    const int m0 = blockIdx.y * 64, n0 = blockIdx.x * 128;

    const int rr = tid >> 2, ch = tid & 3;
    const __half* pa  = g.A + (size_t)(m0 + rr) * DIMM + ch * 8;
    const __half* pl  = (prod == 2) ? (g.Al + (size_t)(m0 + rr) * DIMM + ch * 8) : g.A;
    const __half* pw0 = g.W + (size_t)(n0 + rr) * DIMM + ch * 8;
    const __half* pw1 = g.W + (size_t)(n0 + rr + 64) * DIMM + ch * 8;
    const uint32_t dA  = sb + rr * 80 + ch * 16;
    const uint32_t dB0 = sb + 2 * PL_A + rr * 80 + ch * 16;
    const uint32_t dB1 = dB0 + 64 * 80;

    const uint32_t aoff = (uint32_t)(wm * 32 + (lane & 15)) * 80 + ((lane >> 4) << 4);
    const uint32_t boff = 2 * PL_A +
        (uint32_t)(wn * 32 + ((lane >> 4) << 3) + (lane & 7)) * 80 + (((lane >> 3) & 1) << 4);

    auto issue = [&](int i) {
        int kk = i * 32;
        uint32_t st = (i % G_NST) * G_STB;
        asm volatile("cp.async.cg.shared.global [%0], [%1], 16;" :: "r"(dA + st), "l"(pa + kk));
        if (prod == 2)
            asm volatile("cp.async.cg.shared.global [%0], [%1], 16;" :: "r"(dA + PL_A + st), "l"(pl + kk));
        asm volatile("cp.async.cg.shared.global [%0], [%1], 16;" :: "r"(dB0 + st), "l"(pw0 + kk));
        asm volatile("cp.async.cg.shared.global [%0], [%1], 16;" :: "r"(dB1 + st), "l"(pw1 + kk));
        asm volatile("cp.async.commit_group;");
    };

    float acc[2][4][4];
    #pragma unroll
    for (int mi = 0; mi < 2; mi++)
        #pragma unroll
        for (int ni = 0; ni < 4; ni++)
            #pragma unroll
            for (int e = 0; e < 4; e++) acc[mi][ni][e] = 0.f;

    #pragma unroll
    for (int s = 0; s < G_NST - 1; s++) issue(s);

    #pragma unroll 1
    for (int i = 0; i < 32; i++) {
        if (31 - i >= G_NST - 2)    asm volatile("cp.async.wait_group %0;" :: "n"(G_NST - 2));
        else                        asm volatile("cp.async.wait_group 0;");
        __syncthreads();
        if (i + G_NST - 1 < 32) issue(i + G_NST - 1);

        uint32_t stb = sb + (i % G_NST) * G_STB;
        #pragma unroll
        for (int ki = 0; ki < 2; ki++) {
            uint32_t koff = ki * 32;
            uint32_t ah[2][4], al[2][4], bf[4][2];
            ldm_x4(ah[0][0], ah[0][1], ah[0][2], ah[0][3], stb + aoff + koff);
            ldm_x4(ah[1][0], ah[1][1], ah[1][2], ah[1][3], stb + aoff + 16 * 80 + koff);
            if (prod == 2) {
                ldm_x4(al[0][0], al[0][1], al[0][2], al[0][3], stb + aoff + PL_A + koff);
                ldm_x4(al[1][0], al[1][1], al[1][2], al[1][3], stb + aoff + PL_A + 16 * 80 + koff);
            }
            ldm_x4(bf[0][0], bf[0][1], bf[1][0], bf[1][1], stb + boff + koff);
            ldm_x4(bf[2][0], bf[2][1], bf[3][0], bf[3][1], stb + boff + 16 * 80 + koff);
            #pragma unroll
            for (int ni = 0; ni < 4; ni++)
                #pragma unroll
                for (int mi = 0; mi < 2; mi++)
                    mma_f16(acc[mi][ni], ah[mi], bf[ni]);
            if (prod == 2) {
                #pragma unroll
                for (int ni = 0; ni < 4; ni++)
                    #pragma unroll
                    for (int mi = 0; mi < 2; mi++)
                        mma_f16(acc[mi][ni], al[mi], bf[ni]);
            }
        }
    }

    const int omode = g.omode;
    #pragma unroll
    for (int ni = 0; ni < 4; ni++) {
        int cg = n0 + wn * 32 + ni * 8 + 2 * gc;
        float b0 = g.bias[cg], b1 = g.bias[cg + 1];
        #pragma unroll
        for (int mi = 0; mi < 2; mi++) {
            int r = m0 + wm * 32 + mi * 16 + gr;
            float v0 = acc[mi][ni][0] + b0;
            float v1 = acc[mi][ni][1] + b1;
            float v2 = acc[mi][ni][2] + b0;
            float v3 = acc[mi][ni][3] + b1;
            if (SILU) {
                v0 = v0 / (1.f + __expf(-v0));
                v1 = v1 / (1.f + __expf(-v1));
                v2 = v2 / (1.f + __expf(-v2));
                v3 = v3 / (1.f + __expf(-v3));
            }
            if (omode == 0) {
                float* C = (float*)g.C;
                *(float2*)(C + (size_t)r * CCH + cg)       = make_float2(v0, v1);
                *(float2*)(C + (size_t)(r + 8) * CCH + cg) = make_float2(v2, v3);
            } else if (omode == 1) {
                __half* C = (__half*)g.C;
                *(uint32_t*)(C + (size_t)r * CCH + cg)       = pack2f16(v0, v1);
                *(uint32_t*)(C + (size_t)(r + 8) * CCH + cg) = pack2f16(v2, v3);
            } else {
                __half* C  = (__half*)g.C;
                __half* Cl = (__half*)g.Cl;
                uint32_t h, l;
                split2h(v0, v1, h, l);
                *(uint32_t*)(C  + (size_t)r * CCH + cg) = h;
                *(uint32_t*)(Cl + (size_t)r * CCH + cg) = l;
                split2h(v2, v3, h, l);
                *(uint32_t*)(C  + (size_t)(r + 8) * CCH + cg) = h;
                *(uint32_t*)(Cl + (size_t)(r + 8) * CCH + cg) = l;
            }
        }
    }
}

// ---------------- fused depthwise conv k=3, vectorized (8 ch/thread) -------------
__global__ void __launch_bounds__(256) dwconv_all_k(
    const uint4* q, const uint4* k, const uint4* vh, const uint4* vl,
    const float* dwt, const float* bq, const float* bk, const float* bv,
    uint4* oq, uint4* ok, uint4* ovh, uint4* ovl)
{
    const int z = blockIdx.y;
    const int i4 = blockIdx.x * 256 + threadIdx.x;   // < 524288
    const int c8 = i4 & 127, m = i4 >> 7, s = m & (SEQ - 1);
    const int c0 = c8 * 8;

    const float* wt = dwt + z * 3 * CCH;
    const float* bb = (z == 0) ? bq : ((z == 1) ? bk : bv);

    float w0[8], w1[8], w2[8], bvv[8];
    *(float4*)&w0[0] = *(const float4*)(wt + c0);
    *(float4*)&w0[4] = *(const float4*)(wt + c0 + 4);
    *(float4*)&w1[0] = *(const float4*)(wt + CCH + c0);
    *(float4*)&w1[4] = *(const float4*)(wt + CCH + c0 + 4);
    *(float4*)&w2[0] = *(const float4*)(wt + 2 * CCH + c0);
    *(float4*)&w2[4] = *(const float4*)(wt + 2 * CCH + c0 + 4);
    *(float4*)&bvv[0] = *(const float4*)(bb + c0);
    *(float4*)&bvv[4] = *(const float4*)(bb + c0 + 4);

    const uint4 zero4 = make_uint4(0, 0, 0, 0);
    float xc_[8], xm_[8], xp_[8];

    if (z < 2) {
        const uint4* in = z ? k : q;
        uint4 xc = in[i4];
        uint4 xm = (s > 0) ? in[i4 - 128] : zero4;
        uint4 xp = (s < SEQ - 1) ? in[i4 + 128] : zero4;
        #pragma unroll
        for (int j = 0; j < 4; j++) {
            float2 a = __half22float2(((const __half2*)&xc)[j]); xc_[2*j] = a.x; xc_[2*j+1] = a.y;
            float2 b = __half22float2(((const __half2*)&xm)[j]); xm_[2*j] = b.x; xm_[2*j+1] = b.y;
            float2 c = __half22float2(((const __half2*)&xp)[j]); xp_[2*j] = c.x; xp_[2*j+1] = c.y;
        }
        uint4 out;
        #pragma unroll
        for (int j = 0; j < 4; j++) {
            float r0 = xm_[2*j]   * w0[2*j]   + xc_[2*j]   * w1[2*j]   + xp_[2*j]   * w2[2*j]   + bvv[2*j];
            float r1 = xm_[2*j+1] * w0[2*j+1] + xc_[2*j+1] * w1[2*j+1] + xp_[2*j+1] * w2[2*j+1] + bvv[2*j+1];
            ((uint32_t*)&out)[j] = pack2f16(r0, r1);
        }
        (z ? ok : oq)[i4] = out;
    } else {
        uint4 xch = vh[i4], xcl = vl[i4];
        uint4 xmh = zero4, xml = zero4, xph = zero4, xpl = zero4;
        if (s > 0)       { xmh = vh[i4 - 128]; xml = vl[i4 - 128]; }
        if (s < SEQ - 1) { xph = vh[i4 + 128]; xpl = vl[i4 + 128]; }
        #pragma unroll
        for (int j = 0; j < 4; j++) {
            float2 ah = __half22float2(((const __half2*)&xch)[j]);
            float2 al = __half22float2(((const __half2*)&xcl)[j]);
            xc_[2*j] = ah.x + al.x; xc_[2*j+1] = ah.y + al.y;
            float2 bh = __half22float2(((const __half2*)&xmh)[j]);
            float2 bl = __half22float2(((const __half2*)&xml)[j]);
            xm_[2*j] = bh.x + bl.x; xm_[2*j+1] = bh.y + bl.y;
            float2 ch = __half22float2(((const __half2*)&xph)[j]);
            float2 cl = __half22float2(((const __half2*)&xpl)[j]);
            xp_[2*j] = ch.x + cl.x; xp_[2*j+1] = ch.y + cl.y;
        }
        uint4 oh, ol;
        #pragma unroll
        for (int j = 0; j < 4; j++) {
            float r0 = xm_[2*j]   * w0[2*j]   + xc_[2*j]   * w1[2*j]   + xp_[2*j]   * w2[2*j]   + bvv[2*j];
            float r1 = xm_[2*j+1] * w0[2*j+1] + xc_[2*j+1] * w1[2*j+1] + xp_[2*j+1] * w2[2*j+1] + bvv[2*j+1];
            uint32_t h, l;
            split2h(r0, r1, h, l);
            ((uint32_t*)&oh)[j] = h;
            ((uint32_t*)&ol)[j] = l;
        }
        ovh[i4] = oh;
        ovl[i4] = ol;
    }
}

// ---------------- merged l2norm (z=0:q, z=1:k) + vtrans (z=2) --------------------
__global__ void l2vt_k(const __half2* q, const __half2* k, __half2* qn, __half2* kn,
                       const __half* v, __half* vt)
{
    int z = blockIdx.y;
    if (z < 2) {
        const __half2* src = z ? k : q;
        __half2* dst = z ? kn : qn;
        float sc = z ? 1.0f : 0.125f;
        int warp = threadIdx.x >> 5, lane = threadIdx.x & 31;
        size_t g = (size_t)blockIdx.x * 8 + warp;
        float2 x = __half22float2(src[g * 32 + lane]);
        float ss = x.x * x.x + x.y * x.y;
        #pragma unroll
        for (int o = 16; o; o >>= 1) ss += __shfl_xor_sync(0xffffffffu, ss, o);
        float inv = sc / fmaxf(sqrtf(ss), 1e-12f);
        dst[g * 32 + lane] = __floats2half2_rn(x.x * inv, x.y * inv);
    } else {
        int bx = blockIdx.x;
        if (bx >= 4096) return;
        __shared__ float t[32][33];
        int cB = bx & 31, sB = (bx >> 5) & 63, b = bx >> 11;
        int tx = threadIdx.x & 31, ty = threadIdx.x >> 5;   // 32x8
        int s0 = sB * 32, c0 = cB * 32;
        #pragma unroll
        for (int j = 0; j < 4; j++)
            t[ty + 8 * j][tx] = __half2float(v[(size_t)(b * SEQ + s0 + ty + 8 * j) * CCH + c0 + tx]);
        __syncthreads();
        #pragma unroll
        for (int j = 0; j < 4; j++)
            vt[(size_t)(b * CCH + c0 + ty + 8 * j) * SEQ + s0 + tx] = __float2half(t[tx][ty + 8 * j]);
    }
}

// ================= flash attention: 3-stage cp.async, 3 CTAs/SM ==================
// Split-half QK (s: 16 floats) + early fp16 pack (aF: 16 u32) to fit 85-reg cap.
#define AT_STW 4608
#define AT_NST 3
#define AT_SMEM (AT_NST*AT_STW*4)    // 55296 B

__global__ void __launch_bounds__(256, 3) attn_mma_k(const __half* __restrict__ Qh,
                                                     const __half* __restrict__ Kh,
                                                     const __half* __restrict__ Vt,
                                                     const int* __restrict__ mask,
                                                     __half* __restrict__ AOh,
                                                     __half* __restrict__ AOl)
{
    const int qt = blockIdx.x, h = blockIdx.y, bb = blockIdx.z;
    extern __shared__ uint32_t asw[];
    __shared__ int s_mask[AT_NST][64];

    const int tid = threadIdx.x, lane = tid & 31, w = tid >> 5;
    const int gr = lane >> 2, gc = lane & 3;
    const uint32_t sbase = smem_u32(asw);

    const __half* kb = Kh + ((size_t)bb * SEQ) * CCH + h * HDD;
    const __half* vb = Vt + ((size_t)(bb * NHH + h)) * HDD * SEQ;

    const uint32_t ldmoff =
        (uint32_t)(((lane >> 4) << 3) + (lane & 7)) * 144 + (((lane >> 3) & 1) << 4);

    auto issue = [&](int jt) {
        int slot = jt % AT_NST;
        uint32_t kdst = sbase + slot * AT_STW * 4;
        uint32_t vdst = kdst + 2304 * 4;
        #pragma unroll
        for (int j = 0; j < 2; j++) {
            int c = tid + 256 * j;
            int row = c >> 3, ch = c & 7;
            uint32_t d = kdst + (row * 36 + ch * 4) * 4;
            const __half* s = kb + (size_t)(jt * 64 + row) * CCH + ch * 8;
            asm volatile("cp.async.cg.shared.global [%0], [%1], 16;" :: "r"(d), "l"(s));
        }
        #pragma unroll
        for (int j = 0; j < 2; j++) {
            int c = tid + 256 * j;
            int row = c >> 3, ch = c & 7;
            uint32_t d = vdst + (row * 36 + ch * 4) * 4;
            const __half* s = vb + (size_t)row * SEQ + jt * 64 + ch * 8;
            asm volatile("cp.async.cg.shared.global [%0], [%1], 16;" :: "r"(d), "l"(s));
        }
        if (tid < 16) {
            uint32_t d = smem_u32(&s_mask[slot][0]) + tid * 16;
            const int* s = mask + bb * SEQ + jt * 64 + tid * 4;
            asm volatile("cp.async.cg.shared.global [%0], [%1], 16;" :: "r"(d), "l"(s));
        }
        asm volatile("cp.async.commit_group;");
    };

    issue(0);
    issue(1);

    uint32_t qa[4][4];
    {
        const __half* qb = Qh + ((size_t)(bb * SEQ + qt * 128)) * CCH + h * HDD;
        int r0 = w * 16 + gr, r1 = r0 + 8;
        #pragma unroll
        for (int ks = 0; ks < 4; ks++) {
            int c = ks * 16 + 2 * gc;
            qa[ks][0] = *(const uint32_t*)(qb + (size_t)r0 * CCH + c);
            qa[ks][1] = *(const uint32_t*)(qb + (size_t)r1 * CCH + c);
            qa[ks][2] = *(const uint32_t*)(qb + (size_t)r0 * CCH + c + 8);
            qa[ks][3] = *(const uint32_t*)(qb + (size_t)r1 * CCH + c + 8);
        }
    }

    float o[8][4];
    #pragma unroll
    for (int ht = 0; ht < 8; ht++)
        #pragma unroll
        for (int e = 0; e < 4; e++) o[ht][e] = 0.f;
    float l0 = 0.f, l1 = 0.f;

    #pragma unroll 1
    for (int jt = 0; jt < 32; jt++) {
        const int slot = jt % AT_NST;
        if (jt < 31) asm volatile("cp.async.wait_group 1;");
        else         asm volatile("cp.async.wait_group 0;");
        __syncthreads();
        if (jt + 2 < 32) issue(jt + 2);

        uint32_t kaddr = sbase + slot * AT_STW * 4 + ldmoff;
        uint32_t vaddr = kaddr + 2304 * 4;

        // ---- QK in two nt-halves; pack P to fp16 immediately ----
        uint32_t aF[16];
        #pragma unroll
        for (int half = 0; half < 2; half++) {
            float s[4][4];
            #pragma unroll
            for (int j = 0; j < 4; j++)
                #pragma unroll
                for (int e = 0; e < 4; e++) s[j][e] = 0.f;
            #pragma unroll
            for (int ks = 0; ks < 4; ks++) {
                uint32_t b0, b1, b2, b3, b4, b5, b6, b7;
                ldm_x4(b0, b1, b2, b3, kaddr + (2 * half)     * (16 * 144) + ks * 32);
                ldm_x4(b4, b5, b6, b7, kaddr + (2 * half + 1) * (16 * 144) + ks * 32);
                mma_f16_b(s[0], qa[ks], b0, b1);
                mma_f16_b(s[1], qa[ks], b2, b3);
                mma_f16_b(s[2], qa[ks], b4, b5);
                mma_f16_b(s[3], qa[ks], b6, b7);
            }
            #pragma unroll
            for (int j = 0; j < 4; j++) {
                int c0 = (half * 4 + j) * 8 + 2 * gc;
                bool ok0 = s_mask[slot][c0] != 0;
                bool ok1 = s_mask[slot][c0 + 1] != 0;
                s[j][0] = ok0 ? exp_small(s[j][0]) : 0.f;
                s[j][1] = ok1 ? exp_small(s[j][1]) : 0.f;
                s[j][2] = ok0 ? exp_small(s[j][2]) : 0.f;
                s[j][3] = ok1 ? exp_small(s[j][3]) : 0.f;
                l0 += s[j][0] + s[j][1];
                l1 += s[j][2] + s[j][3];
            }
            int kb8 = half * 8;
            aF[kb8 + 0] = pack2f16(s[0][0], s[0][1]);
            aF[kb8 + 1] = pack2f16(s[0][2], s[0][3]);
            aF[kb8 + 2] = pack2f16(s[1][0], s[1][1]);
            aF[kb8 + 3] = pack2f16(s[1][2], s[1][3]);
            aF[kb8 + 4] = pack2f16(s[2][0], s[2][1]);
            aF[kb8 + 5] = pack2f16(s[2][2], s[2][3]);
            aF[kb8 + 6] = pack2f16(s[3][0], s[3][1]);
            aF[kb8 + 7] = pack2f16(s[3][2], s[3][3]);
        }

        // ---- O += P V (vf loaded one ldmatrix at a time) ----
        #pragma unroll
        for (int ks = 0; ks < 4; ks++) {
            #pragma unroll
            for (int p = 0; p < 4; p++) {
                uint32_t v0, v1, v2, v3;
                ldm_x4(v0, v1, v2, v3, vaddr + p * (16 * 144) + ks * 32);
                mma_f16_b(o[2 * p],     &aF[ks * 4], v0, v1);
                mma_f16_b(o[2 * p + 1], &aF[ks * 4], v2, v3);
            }
        }
    }

    l0 += __shfl_xor_sync(0xffffffffu, l0, 1);
    l0 += __shfl_xor_sync(0xffffffffu, l0, 2);
    l1 += __shfl_xor_sync(0xffffffffu, l1, 1);
    l1 += __shfl_xor_sync(0xffffffffu, l1, 2);
    {
        float inv0 = 1.f / l0, inv1 = 1.f / l1;
        int r0 = w * 16 + gr, r1 = r0 + 8;
        size_t base = ((size_t)(bb * SEQ + qt * 128)) * CCH + h * HDD;
        __half* Oh = AOh + base;
        __half* Ol = AOl + base;
        #pragma unroll
        for (int ht = 0; ht < 8; ht++) {
            int c = ht * 8 + 2 * gc;
            uint32_t hh, ll;
            split2h(o[ht][0] * inv0, o[ht][1] * inv0, hh, ll);
            *(uint32_t*)(Oh + (size_t)r0 * CCH + c) = hh;
            *(uint32_t*)(Ol + (size_t)r0 * CCH + c) = ll;
            split2h(o[ht][2] * inv1, o[ht][3] * inv1, hh, ll);
            *(uint32_t*)(Oh + (size_t)r1 * CCH + c) = hh;
            *(uint32_t*)(Ol + (size_t)r1 * CCH + c) = ll;
        }
    }
}

// ---------------- host launcher ---------------------------------------------------
extern "C" void kernel_launch(void* const* d_in, const int* in_sizes, int n_in,
                              void* d_out, int out_size)
{
    const float* x    = (const float*)d_in[0];
    const int*   mask = (const int*)d_in[1];
    const float* wq   = (const float*)d_in[2];
    const float* bq   = (const float*)d_in[3];
    const float* wk   = (const float*)d_in[4];
    const float* bk   = (const float*)d_in[5];
    const float* wv   = (const float*)d_in[6];
    const float* bv   = (const float*)d_in[7];
    const float* qdww = (const float*)d_in[8];
    const float* qdwb = (const float*)d_in[9];
    const float* qpww = (const float*)d_in[10];
    const float* qpwb = (const float*)d_in[11];
    const float* kdww = (const float*)d_in[12];
    const float* kdwb = (const float*)d_in[13];
    const float* kpww = (const float*)d_in[14];
    const float* kpwb = (const float*)d_in[15];
    const float* vdww = (const float*)d_in[16];
    const float* vdwb = (const float*)d_in[17];
    const float* vpww = (const float*)d_in[18];
    const float* vpwb = (const float*)d_in[19];
    const float* wo   = (const float*)d_in[20];
    const float* bo   = (const float*)d_in[21];
    float* out = (float*)d_out;

    __half *xh, *xlo, *w16, *q16, *k16, *vhi, *vlo, *qc16, *kc16, *vchi, *vclo;
    __half *qpw, *kpw, *vpw, *qn, *kn, *vt, *aoh, *aol;
    float* dwt;
    cudaGetSymbolAddress((void**)&xh,  g_xh);
    cudaGetSymbolAddress((void**)&xlo, g_xlo);
    cudaGetSymbolAddress((void**)&w16, g_w16);
    cudaGetSymbolAddress((void**)&dwt, g_dwt);
    cudaGetSymbolAddress((void**)&q16, g_q16);
    cudaGetSymbolAddress((void**)&k16, g_k16);
    cudaGetSymbolAddress((void**)&vhi, g_vhi);
    cudaGetSymbolAddress((void**)&vlo, g_vlo);
    cudaGetSymbolAddress((void**)&qc16, g_qc16);
    cudaGetSymbolAddress((void**)&kc16, g_kc16);
    cudaGetSymbolAddress((void**)&vchi, g_vchi);
    cudaGetSymbolAddress((void**)&vclo, g_vclo);
    cudaGetSymbolAddress((void**)&qpw, g_qpw);
    cudaGetSymbolAddress((void**)&kpw, g_kpw);
    cudaGetSymbolAddress((void**)&vpw, g_vpw);
    cudaGetSymbolAddress((void**)&qn,  g_qn);
    cudaGetSymbolAddress((void**)&kn,  g_kn);
    cudaGetSymbolAddress((void**)&vt,  g_vt);
    cudaGetSymbolAddress((void**)&aoh, g_aoh);
    cudaGetSymbolAddress((void**)&aol, g_aol);

    __half* wqh  = w16 + 0 * (size_t)DIMM * CCH;
    __half* wkh  = w16 + 1 * (size_t)DIMM * CCH;
    __half* wvh  = w16 + 2 * (size_t)DIMM * CCH;
    __half* qpwh = w16 + 3 * (size_t)DIMM * CCH;
    __half* kpwh = w16 + 4 * (size_t)DIMM * CCH;
    __half* vpwh = w16 + 5 * (size_t)DIMM * CCH;
    __half* woh  = w16 + 6 * (size_t)DIMM * CCH;

    cudaFuncSetAttribute(gemm_h_k<true>,  cudaFuncAttributeMaxDynamicSharedMemorySize, G_SMEM);
    cudaFuncSetAttribute(gemm_h_k<false>, cudaFuncAttributeMaxDynamicSharedMemorySize, G_SMEM);
    cudaFuncSetAttribute(attn_mma_k, cudaFuncAttributeMaxDynamicSharedMemorySize, AT_SMEM);

    // 0) prep: weights (+ transposed dw weights) + x to fp16
    WC wc;
    wc.s[0] = wq;  wc.d[0] = wqh;
    wc.s[1] = wk;  wc.d[1] = wkh;
    wc.s[2] = wv;  wc.d[2] = wvh;
    wc.s[3] = qpww; wc.d[3] = qpwh;
    wc.s[4] = kpww; wc.d[4] = kpwh;
    wc.s[5] = vpww; wc.d[5] = vpwh;
    wc.s[6] = wo;  wc.d[6] = woh;
    wc.dw[0] = qdww; wc.dw[1] = kdww; wc.dw[2] = vdww;
    wc.dwt = dwt;
    wconv_k<<<dim3(2048, 8), 256>>>(wc);
    xconv_k<<<8192, 256>>>((const float2*)x, (uint32_t*)xh, (uint32_t*)xlo);

    dim3 grid_3(8, 64, 3), grid_1(8, 64, 1);

    // 1) QKV projection + SiLU (fused; q,k prod=1, v prod=2)
    gemm_h_k<true><<<grid_3, 256, G_SMEM>>>(
        GH{xh, 0, wqh, bq, q16, 0, 1, 1},
        GH{xh, 0, wkh, bk, k16, 0, 1, 1},
        GH{xh, xlo, wvh, bv, vhi, vlo, 2, 2});

    // 2) depthwise conv (fused q,k,v; vectorized)
    dwconv_all_k<<<dim3(2048, 3), 256>>>(
        (const uint4*)q16, (const uint4*)k16, (const uint4*)vhi, (const uint4*)vlo,
        dwt, qdwb, kdwb, vdwb,
        (uint4*)qc16, (uint4*)kc16, (uint4*)vchi, (uint4*)vclo);

    // 3) pointwise conv (fused)
    gemm_h_k<false><<<grid_3, 256, G_SMEM>>>(
        GH{qc16, 0, qpwh, qpwb, qpw, 0, 1, 1},
        GH{kc16, 0, kpwh, kpwb, kpw, 0, 1, 1},
        GH{vchi, vclo, vpwh, vpwb, vpw, 0, 2, 1});

    // 4) merged l2norm (q scaled 0.125) + v transpose
    l2vt_k<<<dim3(8192, 3), 256>>>((const __half2*)qpw, (const __half2*)kpw,
                                   (__half2*)qn, (__half2*)kn, vpw, vt);

    // 5) flash attention -> fp16 hi/lo (3 CTAs/SM)
    attn_mma_k<<<dim3(SEQ / 128, NHH, BSZ), 256, AT_SMEM>>>(qn, kn, vt, mask, aoh, aol);

    // 6) output projection -> d_out (fp32)
    gemm_h_k<false><<<grid_1, 256, G_SMEM>>>(
        GH{aoh, aol, woh, bo, out, 0, 2, 0},
        GH{aoh, aol, woh, bo, out, 0, 2, 0},
        GH{aoh, aol, woh, bo, out, 0, 2, 0});
}

// round 15
// speedup vs baseline: 1.0387x; 1.0387x over previous
#include <cuda_runtime.h>
#include <cuda_fp16.h>
#include <stdint.h>

#define BSZ 2
#define SEQ 2048
#define DIMM 1024
#define CCH 1024
#define NHH 16
#define HDD 64
#define MROWS (BSZ*SEQ)   // 4096

// ---------------- fp16 scratch (device globals) ----------------------------------
__device__ __half g_xh [MROWS*DIMM];
__device__ __half g_xlo[MROWS*DIMM];
__device__ __half g_w16[7][DIMM*CCH];          // wq,wk,wv,qpw,kpw,vpw,wo
__device__ float  g_dwt[3*3*CCH];              // transposed dw weights [qkv][tap][C]
__device__ __half g_q16[MROWS*CCH],  g_k16[MROWS*CCH];
__device__ __half g_vhi[MROWS*CCH],  g_vlo[MROWS*CCH];
__device__ __half g_qc16[MROWS*CCH], g_kc16[MROWS*CCH];
__device__ __half g_vchi[MROWS*CCH], g_vclo[MROWS*CCH];
__device__ __half g_qpw[MROWS*CCH],  g_kpw[MROWS*CCH], g_vpw[MROWS*CCH];
__device__ __half g_qn[MROWS*CCH],   g_kn[MROWS*CCH],  g_vt[MROWS*CCH];
__device__ __half g_aoh[MROWS*CCH],  g_aol[MROWS*CCH];

// ================= helpers =======================================================
__device__ __forceinline__ uint32_t smem_u32(const void* p) {
    uint32_t a;
    asm("{ .reg .u64 t; cvta.to.shared.u64 t, %1; cvt.u32.u64 %0, t; }" : "=r"(a) : "l"(p));
    return a;
}
__device__ __forceinline__ uint32_t pack2f16(float x, float y) {
    __half2 t = __floats2half2_rn(x, y);
    return *reinterpret_cast<uint32_t*>(&t);
}
__device__ __forceinline__ void split2h(float x, float y, uint32_t& h, uint32_t& l) {
    __half hx = __float2half_rn(x);
    __half hy = __float2half_rn(y);
    __half2 hp = __halves2half2(hx, hy);
    h = *reinterpret_cast<uint32_t*>(&hp);
    l = pack2f16(x - __half2float(hx), y - __half2float(hy));
}
__device__ __forceinline__ void mma_f16(float* d, const uint32_t* a, const uint32_t* b) {
    asm volatile(
        "mma.sync.aligned.m16n8k16.row.col.f32.f16.f16.f32 "
        "{%0,%1,%2,%3}, {%4,%5,%6,%7}, {%8,%9}, {%0,%1,%2,%3};"
        : "+f"(d[0]), "+f"(d[1]), "+f"(d[2]), "+f"(d[3])
        : "r"(a[0]), "r"(a[1]), "r"(a[2]), "r"(a[3]), "r"(b[0]), "r"(b[1]));
}
__device__ __forceinline__ void mma_f16_b(float* d, const uint32_t* a, uint32_t b0, uint32_t b1) {
    asm volatile(
        "mma.sync.aligned.m16n8k16.row.col.f32.f16.f16.f32 "
        "{%0,%1,%2,%3}, {%4,%5,%6,%7}, {%8,%9}, {%0,%1,%2,%3};"
        : "+f"(d[0]), "+f"(d[1]), "+f"(d[2]), "+f"(d[3])
        : "r"(a[0]), "r"(a[1]), "r"(a[2]), "r"(a[3]), "r"(b0), "r"(b1));
}
__device__ __forceinline__ void ldm_x4(uint32_t& r0, uint32_t& r1, uint32_t& r2, uint32_t& r3,
                                       uint32_t addr) {
    asm volatile("ldmatrix.sync.aligned.m8n8.x4.shared.b16 {%0,%1,%2,%3}, [%4];"
                 : "=r"(r0), "=r"(r1), "=r"(r2), "=r"(r3) : "r"(addr));
}
__device__ __forceinline__ float exp_small(float x) {   // |x| <= 0.125, rel err ~3e-8
    return 1.f + x * (1.f + x * (0.5f + x * (0.166666667f + x * 0.0416666667f)));
}

// ================= merged prep kernel ============================================
// z 0..6: weight fp32->fp16 (512K half2 each); z=7: dw weight transpose;
// z 8..11: x -> hi/lo fp16 (2M float2 in 4 chunks).
struct WC { const float* s[7]; __half* d[7]; const float* dw[3]; float* dwt;
            const float2* x; uint32_t* xh; uint32_t* xl; };
__global__ void prep_k(WC wc)
{
    int z = blockIdx.y;
    int i = blockIdx.x * 256 + threadIdx.x;
    if (z < 7) {
        const float2* s = (const float2*)wc.s[z];
        __half2* d = (__half2*)wc.d[z];
        float2 v = s[i];
        d[i] = __floats2half2_rn(v.x, v.y);
    } else if (z == 7) {
        if (i < 3 * 3 * CCH) {
            int plane = i / (3 * CCH);
            int r = i % (3 * CCH);
            int tap = r >> 10, c = r & (CCH - 1);
            wc.dwt[plane * 3 * CCH + tap * CCH + c] = wc.dw[plane][c * 3 + tap];
        }
    } else {
        int idx = (z - 8) * 524288 + i;
        float2 v = wc.x[idx];
        uint32_t h, l;
        split2h(v.x, v.y, h, l);
        wc.xh[idx] = h; wc.xl[idx] = l;
    }
}

// ================= fp16 GEMM: cp.async + ldmatrix + mma ==========================
struct GH { const __half* A; const __half* Al; const __half* W; const float* bias;
            void* C; void* Cl; int prod; int omode; };

#define PL_A 5120
#define PL_B 10240
#define G_STB (2*PL_A + PL_B)
#define G_NST 3
#define G_SMEM (G_NST*G_STB)         // 61440

template<bool SILU>
__global__ void __launch_bounds__(256, 3)
gemm_h_k(GH g0, GH g1, GH g2)
{
    GH g = (blockIdx.z == 0) ? g0 : ((blockIdx.z == 1) ? g1 : g2);
    const int prod = g.prod;
    extern __shared__ uint32_t smw[];
    const uint32_t sb = smem_u32(smw);

    const int tid = threadIdx.x, lane = tid & 31, wid = tid >> 5;
    const int wm = wid & 1, wn = wid >> 1;
    const int gr = lane >> 2, gc = lane & 3;
    const int m0 = blockIdx.y * 64, n0 = blockIdx.x * 128;

    const int rr = tid >> 2, ch = tid & 3;
    const __half* pa  = g.A + (size_t)(m0 + rr) * DIMM + ch * 8;
    const __half* pl  = (prod == 2) ? (g.Al + (size_t)(m0 + rr) * DIMM + ch * 8) : g.A;
    const __half* pw0 = g.W + (size_t)(n0 + rr) * DIMM + ch * 8;
    const __half* pw1 = g.W + (size_t)(n0 + rr + 64) * DIMM + ch * 8;
    const uint32_t dA  = sb + rr * 80 + ch * 16;
    const uint32_t dB0 = sb + 2 * PL_A + rr * 80 + ch * 16;
    const uint32_t dB1 = dB0 + 64 * 80;

    const uint32_t aoff = (uint32_t)(wm * 32 + (lane & 15)) * 80 + ((lane >> 4) << 4);
    const uint32_t boff = 2 * PL_A +
        (uint32_t)(wn * 32 + ((lane >> 4) << 3) + (lane & 7)) * 80 + (((lane >> 3) & 1) << 4);

    auto issue = [&](int i) {
        int kk = i * 32;
        uint32_t st = (i % G_NST) * G_STB;
        asm volatile("cp.async.cg.shared.global [%0], [%1], 16;" :: "r"(dA + st), "l"(pa + kk));
        if (prod == 2)
            asm volatile("cp.async.cg.shared.global [%0], [%1], 16;" :: "r"(dA + PL_A + st), "l"(pl + kk));
        asm volatile("cp.async.cg.shared.global [%0], [%1], 16;" :: "r"(dB0 + st), "l"(pw0 + kk));
        asm volatile("cp.async.cg.shared.global [%0], [%1], 16;" :: "r"(dB1 + st), "l"(pw1 + kk));
        asm volatile("cp.async.commit_group;");
    };

    float acc[2][4][4];
    #pragma unroll
    for (int mi = 0; mi < 2; mi++)
        #pragma unroll
        for (int ni = 0; ni < 4; ni++)
            #pragma unroll
            for (int e = 0; e < 4; e++) acc[mi][ni][e] = 0.f;

    #pragma unroll
    for (int s = 0; s < G_NST - 1; s++) issue(s);

    #pragma unroll 1
    for (int i = 0; i < 32; i++) {
        if (31 - i >= G_NST - 2)    asm volatile("cp.async.wait_group %0;" :: "n"(G_NST - 2));
        else                        asm volatile("cp.async.wait_group 0;");
        __syncthreads();
        if (i + G_NST - 1 < 32) issue(i + G_NST - 1);

        uint32_t stb = sb + (i % G_NST) * G_STB;
        #pragma unroll
        for (int ki = 0; ki < 2; ki++) {
            uint32_t koff = ki * 32;
            uint32_t ah[2][4], al[2][4], bf[4][2];
            ldm_x4(ah[0][0], ah[0][1], ah[0][2], ah[0][3], stb + aoff + koff);
            ldm_x4(ah[1][0], ah[1][1], ah[1][2], ah[1][3], stb + aoff + 16 * 80 + koff);
            if (prod == 2) {
                ldm_x4(al[0][0], al[0][1], al[0][2], al[0][3], stb + aoff + PL_A + koff);
                ldm_x4(al[1][0], al[1][1], al[1][2], al[1][3], stb + aoff + PL_A + 16 * 80 + koff);
            }
            ldm_x4(bf[0][0], bf[0][1], bf[1][0], bf[1][1], stb + boff + koff);
            ldm_x4(bf[2][0], bf[2][1], bf[3][0], bf[3][1], stb + boff + 16 * 80 + koff);
            #pragma unroll
            for (int ni = 0; ni < 4; ni++)
                #pragma unroll
                for (int mi = 0; mi < 2; mi++)
                    mma_f16(acc[mi][ni], ah[mi], bf[ni]);
            if (prod == 2) {
                #pragma unroll
                for (int ni = 0; ni < 4; ni++)
                    #pragma unroll
                    for (int mi = 0; mi < 2; mi++)
                        mma_f16(acc[mi][ni], al[mi], bf[ni]);
            }
        }
    }

    const int omode = g.omode;
    #pragma unroll
    for (int ni = 0; ni < 4; ni++) {
        int cg = n0 + wn * 32 + ni * 8 + 2 * gc;
        float b0 = g.bias[cg], b1 = g.bias[cg + 1];
        #pragma unroll
        for (int mi = 0; mi < 2; mi++) {
            int r = m0 + wm * 32 + mi * 16 + gr;
            float v0 = acc[mi][ni][0] + b0;
            float v1 = acc[mi][ni][1] + b1;
            float v2 = acc[mi][ni][2] + b0;
            float v3 = acc[mi][ni][3] + b1;
            if (SILU) {
                v0 = v0 / (1.f + __expf(-v0));
                v1 = v1 / (1.f + __expf(-v1));
                v2 = v2 / (1.f + __expf(-v2));
                v3 = v3 / (1.f + __expf(-v3));
            }
            if (omode == 0) {
                float* C = (float*)g.C;
                *(float2*)(C + (size_t)r * CCH + cg)       = make_float2(v0, v1);
                *(float2*)(C + (size_t)(r + 8) * CCH + cg) = make_float2(v2, v3);
            } else if (omode == 1) {
                __half* C = (__half*)g.C;
                *(uint32_t*)(C + (size_t)r * CCH + cg)       = pack2f16(v0, v1);
                *(uint32_t*)(C + (size_t)(r + 8) * CCH + cg) = pack2f16(v2, v3);
            } else {
                __half* C  = (__half*)g.C;
                __half* Cl = (__half*)g.Cl;
                uint32_t h, l;
                split2h(v0, v1, h, l);
                *(uint32_t*)(C  + (size_t)r * CCH + cg) = h;
                *(uint32_t*)(Cl + (size_t)r * CCH + cg) = l;
                split2h(v2, v3, h, l);
                *(uint32_t*)(C  + (size_t)(r + 8) * CCH + cg) = h;
                *(uint32_t*)(Cl + (size_t)(r + 8) * CCH + cg) = l;
            }
        }
    }
}

// ---------------- fused depthwise conv k=3, vectorized (8 ch/thread) -------------
__global__ void __launch_bounds__(256) dwconv_all_k(
    const uint4* q, const uint4* k, const uint4* vh, const uint4* vl,
    const float* dwt, const float* bq, const float* bk, const float* bv,
    uint4* oq, uint4* ok, uint4* ovh, uint4* ovl)
{
    const int z = blockIdx.y;
    const int i4 = blockIdx.x * 256 + threadIdx.x;   // < 524288
    const int c8 = i4 & 127, m = i4 >> 7, s = m & (SEQ - 1);
    const int c0 = c8 * 8;

    const float* wt = dwt + z * 3 * CCH;
    const float* bb = (z == 0) ? bq : ((z == 1) ? bk : bv);

    float w0[8], w1[8], w2[8], bvv[8];
    *(float4*)&w0[0] = *(const float4*)(wt + c0);
    *(float4*)&w0[4] = *(const float4*)(wt + c0 + 4);
    *(float4*)&w1[0] = *(const float4*)(wt + CCH + c0);
    *(float4*)&w1[4] = *(const float4*)(wt + CCH + c0 + 4);
    *(float4*)&w2[0] = *(const float4*)(wt + 2 * CCH + c0);
    *(float4*)&w2[4] = *(const float4*)(wt + 2 * CCH + c0 + 4);
    *(float4*)&bvv[0] = *(const float4*)(bb + c0);
    *(float4*)&bvv[4] = *(const float4*)(bb + c0 + 4);

    const uint4 zero4 = make_uint4(0, 0, 0, 0);
    float xc_[8], xm_[8], xp_[8];

    if (z < 2) {
        const uint4* in = z ? k : q;
        uint4 xc = in[i4];
        uint4 xm = (s > 0) ? in[i4 - 128] : zero4;
        uint4 xp = (s < SEQ - 1) ? in[i4 + 128] : zero4;
        #pragma unroll
        for (int j = 0; j < 4; j++) {
            float2 a = __half22float2(((const __half2*)&xc)[j]); xc_[2*j] = a.x; xc_[2*j+1] = a.y;
            float2 b = __half22float2(((const __half2*)&xm)[j]); xm_[2*j] = b.x; xm_[2*j+1] = b.y;
            float2 c = __half22float2(((const __half2*)&xp)[j]); xp_[2*j] = c.x; xp_[2*j+1] = c.y;
        }
        uint4 out;
        #pragma unroll
        for (int j = 0; j < 4; j++) {
            float r0 = xm_[2*j]   * w0[2*j]   + xc_[2*j]   * w1[2*j]   + xp_[2*j]   * w2[2*j]   + bvv[2*j];
            float r1 = xm_[2*j+1] * w0[2*j+1] + xc_[2*j+1] * w1[2*j+1] + xp_[2*j+1] * w2[2*j+1] + bvv[2*j+1];
            ((uint32_t*)&out)[j] = pack2f16(r0, r1);
        }
        (z ? ok : oq)[i4] = out;
    } else {
        uint4 xch = vh[i4], xcl = vl[i4];
        uint4 xmh = zero4, xml = zero4, xph = zero4, xpl = zero4;
        if (s > 0)       { xmh = vh[i4 - 128]; xml = vl[i4 - 128]; }
        if (s < SEQ - 1) { xph = vh[i4 + 128]; xpl = vl[i4 + 128]; }
        #pragma unroll
        for (int j = 0; j < 4; j++) {
            float2 ah = __half22float2(((const __half2*)&xch)[j]);
            float2 al = __half22float2(((const __half2*)&xcl)[j]);
            xc_[2*j] = ah.x + al.x; xc_[2*j+1] = ah.y + al.y;
            float2 bh = __half22float2(((const __half2*)&xmh)[j]);
            float2 bl = __half22float2(((const __half2*)&xml)[j]);
            xm_[2*j] = bh.x + bl.x; xm_[2*j+1] = bh.y + bl.y;
            float2 ch = __half22float2(((const __half2*)&xph)[j]);
            float2 cl = __half22float2(((const __half2*)&xpl)[j]);
            xp_[2*j] = ch.x + cl.x; xp_[2*j+1] = ch.y + cl.y;
        }
        uint4 oh, ol;
        #pragma unroll
        for (int j = 0; j < 4; j++) {
            float r0 = xm_[2*j]   * w0[2*j]   + xc_[2*j]   * w1[2*j]   + xp_[2*j]   * w2[2*j]   + bvv[2*j];
            float r1 = xm_[2*j+1] * w0[2*j+1] + xc_[2*j+1] * w1[2*j+1] + xp_[2*j+1] * w2[2*j+1] + bvv[2*j+1];
            uint32_t h, l;
            split2h(r0, r1, h, l);
            ((uint32_t*)&oh)[j] = h;
            ((uint32_t*)&ol)[j] = l;
        }
        ovh[i4] = oh;
        ovl[i4] = ol;
    }
}

// ---------------- merged l2norm (z=0:q, z=1:k) + vtrans (z=2) --------------------
__global__ void l2vt_k(const __half2* q, const __half2* k, __half2* qn, __half2* kn,
                       const __half* v, __half* vt)
{
    int z = blockIdx.y;
    if (z < 2) {
        const __half2* src = z ? k : q;
        __half2* dst = z ? kn : qn;
        float sc = z ? 1.0f : 0.125f;
        int warp = threadIdx.x >> 5, lane = threadIdx.x & 31;
        size_t g = (size_t)blockIdx.x * 8 + warp;
        float2 x = __half22float2(src[g * 32 + lane]);
        float ss = x.x * x.x + x.y * x.y;
        #pragma unroll
        for (int o = 16; o; o >>= 1) ss += __shfl_xor_sync(0xffffffffu, ss, o);
        float inv = sc / fmaxf(sqrtf(ss), 1e-12f);
        dst[g * 32 + lane] = __floats2half2_rn(x.x * inv, x.y * inv);
    } else {
        int bx = blockIdx.x;
        if (bx >= 4096) return;
        __shared__ float t[32][33];
        int cB = bx & 31, sB = (bx >> 5) & 63, b = bx >> 11;
        int tx = threadIdx.x & 31, ty = threadIdx.x >> 5;   // 32x8
        int s0 = sB * 32, c0 = cB * 32;
        #pragma unroll
        for (int j = 0; j < 4; j++)
            t[ty + 8 * j][tx] = __half2float(v[(size_t)(b * SEQ + s0 + ty + 8 * j) * CCH + c0 + tx]);
        __syncthreads();
        #pragma unroll
        for (int j = 0; j < 4; j++)
            vt[(size_t)(b * CCH + c0 + ty + 8 * j) * SEQ + s0 + tx] = __float2half(t[tx][ty + 8 * j]);
    }
}

// ================= flash attention: cp.async + ldmatrix fp16, 4-stage, occ 2 =====
#define AT_STW 4608
#define AT_NST 4
#define AT_SMEM (AT_NST*AT_STW*4)    // 73728 B

__global__ void __launch_bounds__(256, 2) attn_mma_k(const __half* __restrict__ Qh,
                                                     const __half* __restrict__ Kh,
                                                     const __half* __restrict__ Vt,
                                                     const int* __restrict__ mask,
                                                     __half* __restrict__ AOh,
                                                     __half* __restrict__ AOl)
{
    const int qt = blockIdx.x, h = blockIdx.y, bb = blockIdx.z;
    extern __shared__ uint32_t asw[];
    __shared__ int s_mask[AT_NST][64];

    const int tid = threadIdx.x, lane = tid & 31, w = tid >> 5;
    const int gr = lane >> 2, gc = lane & 3;
    const uint32_t sbase = smem_u32(asw);

    const __half* kb = Kh + ((size_t)bb * SEQ) * CCH + h * HDD;
    const __half* vb = Vt + ((size_t)(bb * NHH + h)) * HDD * SEQ;

    const uint32_t ldmoff =
        (uint32_t)(((lane >> 4) << 3) + (lane & 7)) * 144 + (((lane >> 3) & 1) << 4);

    auto issue = [&](int jt) {
        int slot = jt % AT_NST;
        uint32_t kdst = sbase + slot * AT_STW * 4;
        uint32_t vdst = kdst + 2304 * 4;
        #pragma unroll
        for (int j = 0; j < 2; j++) {
            int c = tid + 256 * j;
            int row = c >> 3, ch = c & 7;
            uint32_t d = kdst + (row * 36 + ch * 4) * 4;
            const __half* s = kb + (size_t)(jt * 64 + row) * CCH + ch * 8;
            asm volatile("cp.async.cg.shared.global [%0], [%1], 16;" :: "r"(d), "l"(s));
        }
        #pragma unroll
        for (int j = 0; j < 2; j++) {
            int c = tid + 256 * j;
            int row = c >> 3, ch = c & 7;
            uint32_t d = vdst + (row * 36 + ch * 4) * 4;
            const __half* s = vb + (size_t)row * SEQ + jt * 64 + ch * 8;
            asm volatile("cp.async.cg.shared.global [%0], [%1], 16;" :: "r"(d), "l"(s));
        }
        if (tid < 16) {
            uint32_t d = smem_u32(&s_mask[slot][0]) + tid * 16;
            const int* s = mask + bb * SEQ + jt * 64 + tid * 4;
            asm volatile("cp.async.cg.shared.global [%0], [%1], 16;" :: "r"(d), "l"(s));
        }
        asm volatile("cp.async.commit_group;");
    };

    issue(0);
    issue(1);
    issue(2);

    uint32_t qa[4][4];
    {
        const __half* qb = Qh + ((size_t)(bb * SEQ + qt * 128)) * CCH + h * HDD;
        int r0 = w * 16 + gr, r1 = r0 + 8;
        #pragma unroll
        for (int ks = 0; ks < 4; ks++) {
            int c = ks * 16 + 2 * gc;
            qa[ks][0] = *(const uint32_t*)(qb + (size_t)r0 * CCH + c);
            qa[ks][1] = *(const uint32_t*)(qb + (size_t)r1 * CCH + c);
            qa[ks][2] = *(const uint32_t*)(qb + (size_t)r0 * CCH + c + 8);
            qa[ks][3] = *(const uint32_t*)(qb + (size_t)r1 * CCH + c + 8);
        }
    }

    float o[8][4];
    #pragma unroll
    for (int ht = 0; ht < 8; ht++)
        #pragma unroll
        for (int e = 0; e < 4; e++) o[ht][e] = 0.f;
    float l0 = 0.f, l1 = 0.f;

    #pragma unroll 1
    for (int jt = 0; jt < 32; jt++) {
        const int slot = jt % AT_NST;
        int rem = 31 - jt;
        if (rem >= 2)      asm volatile("cp.async.wait_group 2;");
        else if (rem == 1) asm volatile("cp.async.wait_group 1;");
        else               asm volatile("cp.async.wait_group 0;");
        __syncthreads();
        if (jt + 3 < 32) issue(jt + 3);

        uint32_t kaddr = sbase + slot * AT_STW * 4 + ldmoff;
        uint32_t vaddr = kaddr + 2304 * 4;

        float s[8][4];
        #pragma unroll
        for (int nt = 0; nt < 8; nt++)
            #pragma unroll
            for (int e = 0; e < 4; e++) s[nt][e] = 0.f;
        #pragma unroll
        for (int ks = 0; ks < 4; ks++) {
            uint32_t bf[8][2];
            #pragma unroll
            for (int p = 0; p < 4; p++)
                ldm_x4(bf[2 * p][0], bf[2 * p][1], bf[2 * p + 1][0], bf[2 * p + 1][1],
                       kaddr + p * (16 * 144) + ks * 32);
            #pragma unroll
            for (int nt = 0; nt < 8; nt++)
                mma_f16_b(s[nt], qa[ks], bf[nt][0], bf[nt][1]);
        }

        #pragma unroll
        for (int nt = 0; nt < 8; nt++) {
            int c0 = nt * 8 + 2 * gc;
            bool ok0 = s_mask[slot][c0] != 0;
            bool ok1 = s_mask[slot][c0 + 1] != 0;
            s[nt][0] = ok0 ? exp_small(s[nt][0]) : 0.f;
            s[nt][1] = ok1 ? exp_small(s[nt][1]) : 0.f;
            s[nt][2] = ok0 ? exp_small(s[nt][2]) : 0.f;
            s[nt][3] = ok1 ? exp_small(s[nt][3]) : 0.f;
            l0 += s[nt][0] + s[nt][1];
            l1 += s[nt][2] + s[nt][3];
        }

        #pragma unroll
        for (int ks = 0; ks < 4; ks++) {
            uint32_t aF[4];
            aF[0] = pack2f16(s[2 * ks][0],     s[2 * ks][1]);
            aF[1] = pack2f16(s[2 * ks][2],     s[2 * ks][3]);
            aF[2] = pack2f16(s[2 * ks + 1][0], s[2 * ks + 1][1]);
            aF[3] = pack2f16(s[2 * ks + 1][2], s[2 * ks + 1][3]);
            uint32_t vf[8][2];
            #pragma unroll
            for (int p = 0; p < 4; p++)
                ldm_x4(vf[2 * p][0], vf[2 * p][1], vf[2 * p + 1][0], vf[2 * p + 1][1],
                       vaddr + p * (16 * 144) + ks * 32);
            #pragma unroll
            for (int ht = 0; ht < 8; ht++)
                mma_f16_b(o[ht], aF, vf[ht][0], vf[ht][1]);
        }
    }

    l0 += __shfl_xor_sync(0xffffffffu, l0, 1);
    l0 += __shfl_xor_sync(0xffffffffu, l0, 2);
    l1 += __shfl_xor_sync(0xffffffffu, l1, 1);
    l1 += __shfl_xor_sync(0xffffffffu, l1, 2);
    {
        float inv0 = 1.f / l0, inv1 = 1.f / l1;
        int r0 = w * 16 + gr, r1 = r0 + 8;
        size_t base = ((size_t)(bb * SEQ + qt * 128)) * CCH + h * HDD;
        __half* Oh = AOh + base;
        __half* Ol = AOl + base;
        #pragma unroll
        for (int ht = 0; ht < 8; ht++) {
            int c = ht * 8 + 2 * gc;
            uint32_t hh, ll;
            split2h(o[ht][0] * inv0, o[ht][1] * inv0, hh, ll);
            *(uint32_t*)(Oh + (size_t)r0 * CCH + c) = hh;
            *(uint32_t*)(Ol + (size_t)r0 * CCH + c) = ll;
            split2h(o[ht][2] * inv1, o[ht][3] * inv1, hh, ll);
            *(uint32_t*)(Oh + (size_t)r1 * CCH + c) = hh;
            *(uint32_t*)(Ol + (size_t)r1 * CCH + c) = ll;
        }
    }
}

// ---------------- host launcher ---------------------------------------------------
extern "C" void kernel_launch(void* const* d_in, const int* in_sizes, int n_in,
                              void* d_out, int out_size)
{
    const float* x    = (const float*)d_in[0];
    const int*   mask = (const int*)d_in[1];
    const float* wq   = (const float*)d_in[2];
    const float* bq   = (const float*)d_in[3];
    const float* wk   = (const float*)d_in[4];
    const float* bk   = (const float*)d_in[5];
    const float* wv   = (const float*)d_in[6];
    const float* bv   = (const float*)d_in[7];
    const float* qdww = (const float*)d_in[8];
    const float* qdwb = (const float*)d_in[9];
    const float* qpww = (const float*)d_in[10];
    const float* qpwb = (const float*)d_in[11];
    const float* kdww = (const float*)d_in[12];
    const float* kdwb = (const float*)d_in[13];
    const float* kpww = (const float*)d_in[14];
    const float* kpwb = (const float*)d_in[15];
    const float* vdww = (const float*)d_in[16];
    const float* vdwb = (const float*)d_in[17];
    const float* vpww = (const float*)d_in[18];
    const float* vpwb = (const float*)d_in[19];
    const float* wo   = (const float*)d_in[20];
    const float* bo   = (const float*)d_in[21];
    float* out = (float*)d_out;

    __half *xh, *xlo, *w16, *q16, *k16, *vhi, *vlo, *qc16, *kc16, *vchi, *vclo;
    __half *qpw, *kpw, *vpw, *qn, *kn, *vt, *aoh, *aol;
    float* dwt;
    cudaGetSymbolAddress((void**)&xh,  g_xh);
    cudaGetSymbolAddress((void**)&xlo, g_xlo);
    cudaGetSymbolAddress((void**)&w16, g_w16);
    cudaGetSymbolAddress((void**)&dwt, g_dwt);
    cudaGetSymbolAddress((void**)&q16, g_q16);
    cudaGetSymbolAddress((void**)&k16, g_k16);
    cudaGetSymbolAddress((void**)&vhi, g_vhi);
    cudaGetSymbolAddress((void**)&vlo, g_vlo);
    cudaGetSymbolAddress((void**)&qc16, g_qc16);
    cudaGetSymbolAddress((void**)&kc16, g_kc16);
    cudaGetSymbolAddress((void**)&vchi, g_vchi);
    cudaGetSymbolAddress((void**)&vclo, g_vclo);
    cudaGetSymbolAddress((void**)&qpw, g_qpw);
    cudaGetSymbolAddress((void**)&kpw, g_kpw);
    cudaGetSymbolAddress((void**)&vpw, g_vpw);
    cudaGetSymbolAddress((void**)&qn,  g_qn);
    cudaGetSymbolAddress((void**)&kn,  g_kn);
    cudaGetSymbolAddress((void**)&vt,  g_vt);
    cudaGetSymbolAddress((void**)&aoh, g_aoh);
    cudaGetSymbolAddress((void**)&aol, g_aol);

    __half* wqh  = w16 + 0 * (size_t)DIMM * CCH;
    __half* wkh  = w16 + 1 * (size_t)DIMM * CCH;
    __half* wvh  = w16 + 2 * (size_t)DIMM * CCH;
    __half* qpwh = w16 + 3 * (size_t)DIMM * CCH;
    __half* kpwh = w16 + 4 * (size_t)DIMM * CCH;
    __half* vpwh = w16 + 5 * (size_t)DIMM * CCH;
    __half* woh  = w16 + 6 * (size_t)DIMM * CCH;

    cudaFuncSetAttribute(gemm_h_k<true>,  cudaFuncAttributeMaxDynamicSharedMemorySize, G_SMEM);
    cudaFuncSetAttribute(gemm_h_k<false>, cudaFuncAttributeMaxDynamicSharedMemorySize, G_SMEM);
    cudaFuncSetAttribute(attn_mma_k, cudaFuncAttributeMaxDynamicSharedMemorySize, AT_SMEM);

    // 0) merged prep: weights + dw transpose + x hi/lo, one launch
    WC wc;
    wc.s[0] = wq;  wc.d[0] = wqh;
    wc.s[1] = wk;  wc.d[1] = wkh;
    wc.s[2] = wv;  wc.d[2] = wvh;
    wc.s[3] = qpww; wc.d[3] = qpwh;
    wc.s[4] = kpww; wc.d[4] = kpwh;
    wc.s[5] = vpww; wc.d[5] = vpwh;
    wc.s[6] = wo;  wc.d[6] = woh;
    wc.dw[0] = qdww; wc.dw[1] = kdww; wc.dw[2] = vdww;
    wc.dwt = dwt;
    wc.x = (const float2*)x; wc.xh = (uint32_t*)xh; wc.xl = (uint32_t*)xlo;
    prep_k<<<dim3(2048, 12), 256>>>(wc);

    dim3 grid_3(8, 64, 3), grid_1(8, 64, 1);

    // 1) QKV projection + SiLU (fused; q,k prod=1, v prod=2)
    gemm_h_k<true><<<grid_3, 256, G_SMEM>>>(
        GH{xh, 0, wqh, bq, q16, 0, 1, 1},
        GH{xh, 0, wkh, bk, k16, 0, 1, 1},
        GH{xh, xlo, wvh, bv, vhi, vlo, 2, 2});

    // 2) depthwise conv (fused q,k,v; vectorized)
    dwconv_all_k<<<dim3(2048, 3), 256>>>(
        (const uint4*)q16, (const uint4*)k16, (const uint4*)vhi, (const uint4*)vlo,
        dwt, qdwb, kdwb, vdwb,
        (uint4*)qc16, (uint4*)kc16, (uint4*)vchi, (uint4*)vclo);

    // 3) pointwise conv (fused)
    gemm_h_k<false><<<grid_3, 256, G_SMEM>>>(
        GH{qc16, 0, qpwh, qpwb, qpw, 0, 1, 1},
        GH{kc16, 0, kpwh, kpwb, kpw, 0, 1, 1},
        GH{vchi, vclo, vpwh, vpwb, vpw, 0, 2, 1});

    // 4) merged l2norm (q scaled 0.125) + v transpose
    l2vt_k<<<dim3(8192, 3), 256>>>((const __half2*)qpw, (const __half2*)kpw,
                                   (__half2*)qn, (__half2*)kn, vpw, vt);

    // 5) flash attention -> fp16 hi/lo (4-stage, occ 2 — R12 config)
    attn_mma_k<<<dim3(SEQ / 128, NHH, BSZ), 256, AT_SMEM>>>(qn, kn, vt, mask, aoh, aol);

    // 6) output projection -> d_out (fp32)
    gemm_h_k<false><<<grid_1, 256, G_SMEM>>>(
        GH{aoh, aol, woh, bo, out, 0, 2, 0},
        GH{aoh, aol, woh, bo, out, 0, 2, 0},
        GH{aoh, aol, woh, bo, out, 0, 2, 0});
}

// round 16
// speedup vs baseline: 1.2063x; 1.1614x over previous
#include <cuda_runtime.h>
#include <cuda_fp16.h>
#include <stdint.h>

#define BSZ 2
#define SEQ 2048
#define DIMM 1024
#define CCH 1024
#define NHH 16
#define HDD 64
#define MROWS (BSZ*SEQ)   // 4096

// ---------------- fp16 scratch (device globals) ----------------------------------
__device__ __half g_xh [MROWS*DIMM];
__device__ __half g_w16[7][DIMM*CCH];          // wq,wk,wv,qpw,kpw,vpw,wo
__device__ float  g_dwt[3*3*CCH];              // transposed dw weights [qkv][tap][C]
__device__ __half g_q16[MROWS*CCH],  g_k16[MROWS*CCH], g_v16[MROWS*CCH];
__device__ __half g_qc16[MROWS*CCH], g_kc16[MROWS*CCH], g_vc16[MROWS*CCH];
__device__ __half g_qpw[MROWS*CCH],  g_kpw[MROWS*CCH],  g_vpw[MROWS*CCH];
__device__ __half g_qn[MROWS*CCH],   g_kn[MROWS*CCH],   g_vt[MROWS*CCH];
__device__ __half g_aoh[MROWS*CCH];

// ================= helpers =======================================================
__device__ __forceinline__ uint32_t smem_u32(const void* p) {
    uint32_t a;
    asm("{ .reg .u64 t; cvta.to.shared.u64 t, %1; cvt.u32.u64 %0, t; }" : "=r"(a) : "l"(p));
    return a;
}
__device__ __forceinline__ uint32_t pack2f16(float x, float y) {
    __half2 t = __floats2half2_rn(x, y);
    return *reinterpret_cast<uint32_t*>(&t);
}
__device__ __forceinline__ void mma_f16(float* d, const uint32_t* a, const uint32_t* b) {
    asm volatile(
        "mma.sync.aligned.m16n8k16.row.col.f32.f16.f16.f32 "
        "{%0,%1,%2,%3}, {%4,%5,%6,%7}, {%8,%9}, {%0,%1,%2,%3};"
        : "+f"(d[0]), "+f"(d[1]), "+f"(d[2]), "+f"(d[3])
        : "r"(a[0]), "r"(a[1]), "r"(a[2]), "r"(a[3]), "r"(b[0]), "r"(b[1]));
}
__device__ __forceinline__ void mma_f16_b(float* d, const uint32_t* a, uint32_t b0, uint32_t b1) {
    asm volatile(
        "mma.sync.aligned.m16n8k16.row.col.f32.f16.f16.f32 "
        "{%0,%1,%2,%3}, {%4,%5,%6,%7}, {%8,%9}, {%0,%1,%2,%3};"
        : "+f"(d[0]), "+f"(d[1]), "+f"(d[2]), "+f"(d[3])
        : "r"(a[0]), "r"(a[1]), "r"(a[2]), "r"(a[3]), "r"(b0), "r"(b1));
}
__device__ __forceinline__ void ldm_x4(uint32_t& r0, uint32_t& r1, uint32_t& r2, uint32_t& r3,
                                       uint32_t addr) {
    asm volatile("ldmatrix.sync.aligned.m8n8.x4.shared.b16 {%0,%1,%2,%3}, [%4];"
                 : "=r"(r0), "=r"(r1), "=r"(r2), "=r"(r3) : "r"(addr));
}
__device__ __forceinline__ float exp_small(float x) {   // |x| <= 0.125, rel err ~3e-8
    return 1.f + x * (1.f + x * (0.5f + x * (0.166666667f + x * 0.0416666667f)));
}

// ================= merged prep kernel ============================================
// z 0..6: weight fp32->fp16 (512K half2 each); z=7: dw weight transpose;
// z 8..11: x -> fp16 (2M float2 in 4 chunks).
struct WC { const float* s[7]; __half* d[7]; const float* dw[3]; float* dwt;
            const float2* x; uint32_t* xh; };
__global__ void prep_k(WC wc)
{
    int z = blockIdx.y;
    int i = blockIdx.x * 256 + threadIdx.x;
    if (z < 7) {
        const float2* s = (const float2*)wc.s[z];
        __half2* d = (__half2*)wc.d[z];
        float2 v = s[i];
        d[i] = __floats2half2_rn(v.x, v.y);
    } else if (z == 7) {
        if (i < 3 * 3 * CCH) {
            int plane = i / (3 * CCH);
            int r = i % (3 * CCH);
            int tap = r >> 10, c = r & (CCH - 1);
            wc.dwt[plane * 3 * CCH + tap * CCH + c] = wc.dw[plane][c * 3 + tap];
        }
    } else {
        int idx = (z - 8) * 524288 + i;
        float2 v = wc.x[idx];
        wc.xh[idx] = pack2f16(v.x, v.y);
    }
}

// ================= fp16 GEMM (single-product): cp.async + ldmatrix + mma =========
// C[m,n] = sum_k A[m,k]*W[n,k] + bias[n]; M=4096, N=K=1024. fp16 in.
// omode runtime: 0=f32 out, 1=f16 out. CTA 64x128, KC=32, 256 thr, 4 stages,
// 3 CTAs/SM.
struct GH { const __half* A; const __half* W; const float* bias; void* C; int omode; };

#define PL_A 5120
#define PL_B 10240
#define G_STB (PL_A + PL_B)          // 15360
#define G_NST 4
#define G_SMEM (G_NST*G_STB)         // 61440

template<bool SILU>
__global__ void __launch_bounds__(256, 3)
gemm_h_k(GH g0, GH g1, GH g2)
{
    GH g = (blockIdx.z == 0) ? g0 : ((blockIdx.z == 1) ? g1 : g2);
    extern __shared__ uint32_t smw[];
    const uint32_t sb = smem_u32(smw);

    const int tid = threadIdx.x, lane = tid & 31, wid = tid >> 5;
    const int wm = wid & 1, wn = wid >> 1;
    const int gr = lane >> 2, gc = lane & 3;
    const int m0 = blockIdx.y * 64, n0 = blockIdx.x * 128;

    const int rr = tid >> 2, ch = tid & 3;
    const __half* pa  = g.A + (size_t)(m0 + rr) * DIMM + ch * 8;
    const __half* pw0 = g.W + (size_t)(n0 + rr) * DIMM + ch * 8;
    const __half* pw1 = g.W + (size_t)(n0 + rr + 64) * DIMM + ch * 8;
    const uint32_t dA  = sb + rr * 80 + ch * 16;
    const uint32_t dB0 = sb + PL_A + rr * 80 + ch * 16;
    const uint32_t dB1 = dB0 + 64 * 80;

    const uint32_t aoff = (uint32_t)(wm * 32 + (lane & 15)) * 80 + ((lane >> 4) << 4);
    const uint32_t boff = PL_A +
        (uint32_t)(wn * 32 + ((lane >> 4) << 3) + (lane & 7)) * 80 + (((lane >> 3) & 1) << 4);

    auto issue = [&](int i) {
        int kk = i * 32;
        uint32_t st = (i % G_NST) * G_STB;
        asm volatile("cp.async.cg.shared.global [%0], [%1], 16;" :: "r"(dA + st), "l"(pa + kk));
        asm volatile("cp.async.cg.shared.global [%0], [%1], 16;" :: "r"(dB0 + st), "l"(pw0 + kk));
        asm volatile("cp.async.cg.shared.global [%0], [%1], 16;" :: "r"(dB1 + st), "l"(pw1 + kk));
        asm volatile("cp.async.commit_group;");
    };

    float acc[2][4][4];
    #pragma unroll
    for (int mi = 0; mi < 2; mi++)
        #pragma unroll
        for (int ni = 0; ni < 4; ni++)
            #pragma unroll
            for (int e = 0; e < 4; e++) acc[mi][ni][e] = 0.f;

    issue(0); issue(1); issue(2);

    #pragma unroll 1
    for (int i = 0; i < 32; i++) {
        int rem = 31 - i;
        if (rem >= 2)      asm volatile("cp.async.wait_group 2;");
        else if (rem == 1) asm volatile("cp.async.wait_group 1;");
        else               asm volatile("cp.async.wait_group 0;");
        __syncthreads();
        if (i + 3 < 32) issue(i + 3);

        uint32_t stb = sb + (i % G_NST) * G_STB;
        #pragma unroll
        for (int ki = 0; ki < 2; ki++) {
            uint32_t koff = ki * 32;
            uint32_t ah[2][4], bf[4][2];
            ldm_x4(ah[0][0], ah[0][1], ah[0][2], ah[0][3], stb + aoff + koff);
            ldm_x4(ah[1][0], ah[1][1], ah[1][2], ah[1][3], stb + aoff + 16 * 80 + koff);
            ldm_x4(bf[0][0], bf[0][1], bf[1][0], bf[1][1], stb + boff + koff);
            ldm_x4(bf[2][0], bf[2][1], bf[3][0], bf[3][1], stb + boff + 16 * 80 + koff);
            #pragma unroll
            for (int ni = 0; ni < 4; ni++)
                #pragma unroll
                for (int mi = 0; mi < 2; mi++)
                    mma_f16(acc[mi][ni], ah[mi], bf[ni]);
        }
    }

    const int omode = g.omode;
    #pragma unroll
    for (int ni = 0; ni < 4; ni++) {
        int cg = n0 + wn * 32 + ni * 8 + 2 * gc;
        float b0 = g.bias[cg], b1 = g.bias[cg + 1];
        #pragma unroll
        for (int mi = 0; mi < 2; mi++) {
            int r = m0 + wm * 32 + mi * 16 + gr;
            float v0 = acc[mi][ni][0] + b0;
            float v1 = acc[mi][ni][1] + b1;
            float v2 = acc[mi][ni][2] + b0;
            float v3 = acc[mi][ni][3] + b1;
            if (SILU) {
                v0 = v0 / (1.f + __expf(-v0));
                v1 = v1 / (1.f + __expf(-v1));
                v2 = v2 / (1.f + __expf(-v2));
                v3 = v3 / (1.f + __expf(-v3));
            }
            if (omode == 0) {
                float* C = (float*)g.C;
                *(float2*)(C + (size_t)r * CCH + cg)       = make_float2(v0, v1);
                *(float2*)(C + (size_t)(r + 8) * CCH + cg) = make_float2(v2, v3);
            } else {
                __half* C = (__half*)g.C;
                *(uint32_t*)(C + (size_t)r * CCH + cg)       = pack2f16(v0, v1);
                *(uint32_t*)(C + (size_t)(r + 8) * CCH + cg) = pack2f16(v2, v3);
            }
        }
    }
}

// ---------------- fused depthwise conv k=3, vectorized (8 ch/thread), fp16 -------
__global__ void __launch_bounds__(256) dwconv_all_k(
    const uint4* q, const uint4* k, const uint4* v,
    const float* dwt, const float* bq, const float* bk, const float* bv,
    uint4* oq, uint4* ok, uint4* ov)
{
    const int z = blockIdx.y;
    const int i4 = blockIdx.x * 256 + threadIdx.x;   // < 524288
    const int c8 = i4 & 127, m = i4 >> 7, s = m & (SEQ - 1);
    const int c0 = c8 * 8;

    const float* wt = dwt + z * 3 * CCH;
    const float* bb = (z == 0) ? bq : ((z == 1) ? bk : bv);
    const uint4* in = (z == 0) ? q : ((z == 1) ? k : v);
    uint4* out      = (z == 0) ? oq : ((z == 1) ? ok : ov);

    float w0[8], w1[8], w2[8], bvv[8];
    *(float4*)&w0[0] = *(const float4*)(wt + c0);
    *(float4*)&w0[4] = *(const float4*)(wt + c0 + 4);
    *(float4*)&w1[0] = *(const float4*)(wt + CCH + c0);
    *(float4*)&w1[4] = *(const float4*)(wt + CCH + c0 + 4);
    *(float4*)&w2[0] = *(const float4*)(wt + 2 * CCH + c0);
    *(float4*)&w2[4] = *(const float4*)(wt + 2 * CCH + c0 + 4);
    *(float4*)&bvv[0] = *(const float4*)(bb + c0);
    *(float4*)&bvv[4] = *(const float4*)(bb + c0 + 4);

    const uint4 zero4 = make_uint4(0, 0, 0, 0);
    uint4 xc = in[i4];
    uint4 xm = (s > 0) ? in[i4 - 128] : zero4;
    uint4 xp = (s < SEQ - 1) ? in[i4 + 128] : zero4;

    float xc_[8], xm_[8], xp_[8];
    #pragma unroll
    for (int j = 0; j < 4; j++) {
        float2 a = __half22float2(((const __half2*)&xc)[j]); xc_[2*j] = a.x; xc_[2*j+1] = a.y;
        float2 b = __half22float2(((const __half2*)&xm)[j]); xm_[2*j] = b.x; xm_[2*j+1] = b.y;
        float2 c = __half22float2(((const __half2*)&xp)[j]); xp_[2*j] = c.x; xp_[2*j+1] = c.y;
    }
    uint4 o4;
    #pragma unroll
    for (int j = 0; j < 4; j++) {
        float r0 = xm_[2*j]   * w0[2*j]   + xc_[2*j]   * w1[2*j]   + xp_[2*j]   * w2[2*j]   + bvv[2*j];
        float r1 = xm_[2*j+1] * w0[2*j+1] + xc_[2*j+1] * w1[2*j+1] + xp_[2*j+1] * w2[2*j+1] + bvv[2*j+1];
        ((uint32_t*)&o4)[j] = pack2f16(r0, r1);
    }
    out[i4] = o4;
}

// ---------------- merged l2norm (z=0:q, z=1:k) + vtrans (z=2) --------------------
__global__ void l2vt_k(const __half2* q, const __half2* k, __half2* qn, __half2* kn,
                       const __half* v, __half* vt)
{
    int z = blockIdx.y;
    if (z < 2) {
        const __half2* src = z ? k : q;
        __half2* dst = z ? kn : qn;
        float sc = z ? 1.0f : 0.125f;
        int warp = threadIdx.x >> 5, lane = threadIdx.x & 31;
        size_t g = (size_t)blockIdx.x * 8 + warp;
        float2 x = __half22float2(src[g * 32 + lane]);
        float ss = x.x * x.x + x.y * x.y;
        #pragma unroll
        for (int o = 16; o; o >>= 1) ss += __shfl_xor_sync(0xffffffffu, ss, o);
        float inv = sc / fmaxf(sqrtf(ss), 1e-12f);
        dst[g * 32 + lane] = __floats2half2_rn(x.x * inv, x.y * inv);
    } else {
        int bx = blockIdx.x;
        if (bx >= 4096) return;
        __shared__ float t[32][33];
        int cB = bx & 31, sB = (bx >> 5) & 63, b = bx >> 11;
        int tx = threadIdx.x & 31, ty = threadIdx.x >> 5;   // 32x8
        int s0 = sB * 32, c0 = cB * 32;
        #pragma unroll
        for (int j = 0; j < 4; j++)
            t[ty + 8 * j][tx] = __half2float(v[(size_t)(b * SEQ + s0 + ty + 8 * j) * CCH + c0 + tx]);
        __syncthreads();
        #pragma unroll
        for (int j = 0; j < 4; j++)
            vt[(size_t)(b * CCH + c0 + ty + 8 * j) * SEQ + s0 + tx] = __float2half(t[tx][ty + 8 * j]);
    }
}

// ================= flash attention: cp.async + ldmatrix fp16, 4-stage, occ 2 =====
#define AT_STW 4608
#define AT_NST 4
#define AT_SMEM (AT_NST*AT_STW*4)    // 73728 B

__global__ void __launch_bounds__(256, 2) attn_mma_k(const __half* __restrict__ Qh,
                                                     const __half* __restrict__ Kh,
                                                     const __half* __restrict__ Vt,
                                                     const int* __restrict__ mask,
                                                     __half* __restrict__ AOh)
{
    const int qt = blockIdx.x, h = blockIdx.y, bb = blockIdx.z;
    extern __shared__ uint32_t asw[];
    __shared__ int s_mask[AT_NST][64];

    const int tid = threadIdx.x, lane = tid & 31, w = tid >> 5;
    const int gr = lane >> 2, gc = lane & 3;
    const uint32_t sbase = smem_u32(asw);

    const __half* kb = Kh + ((size_t)bb * SEQ) * CCH + h * HDD;
    const __half* vb = Vt + ((size_t)(bb * NHH + h)) * HDD * SEQ;

    const uint32_t ldmoff =
        (uint32_t)(((lane >> 4) << 3) + (lane & 7)) * 144 + (((lane >> 3) & 1) << 4);

    auto issue = [&](int jt) {
        int slot = jt % AT_NST;
        uint32_t kdst = sbase + slot * AT_STW * 4;
        uint32_t vdst = kdst + 2304 * 4;
        #pragma unroll
        for (int j = 0; j < 2; j++) {
            int c = tid + 256 * j;
            int row = c >> 3, ch = c & 7;
            uint32_t d = kdst + (row * 36 + ch * 4) * 4;
            const __half* s = kb + (size_t)(jt * 64 + row) * CCH + ch * 8;
            asm volatile("cp.async.cg.shared.global [%0], [%1], 16;" :: "r"(d), "l"(s));
        }
        #pragma unroll
        for (int j = 0; j < 2; j++) {
            int c = tid + 256 * j;
            int row = c >> 3, ch = c & 7;
            uint32_t d = vdst + (row * 36 + ch * 4) * 4;
            const __half* s = vb + (size_t)row * SEQ + jt * 64 + ch * 8;
            asm volatile("cp.async.cg.shared.global [%0], [%1], 16;" :: "r"(d), "l"(s));
        }
        if (tid < 16) {
            uint32_t d = smem_u32(&s_mask[slot][0]) + tid * 16;
            const int* s = mask + bb * SEQ + jt * 64 + tid * 4;
            asm volatile("cp.async.cg.shared.global [%0], [%1], 16;" :: "r"(d), "l"(s));
        }
        asm volatile("cp.async.commit_group;");
    };

    issue(0);
    issue(1);
    issue(2);

    uint32_t qa[4][4];
    {
        const __half* qb = Qh + ((size_t)(bb * SEQ + qt * 128)) * CCH + h * HDD;
        int r0 = w * 16 + gr, r1 = r0 + 8;
        #pragma unroll
        for (int ks = 0; ks < 4; ks++) {
            int c = ks * 16 + 2 * gc;
            qa[ks][0] = *(const uint32_t*)(qb + (size_t)r0 * CCH + c);
            qa[ks][1] = *(const uint32_t*)(qb + (size_t)r1 * CCH + c);
            qa[ks][2] = *(const uint32_t*)(qb + (size_t)r0 * CCH + c + 8);
            qa[ks][3] = *(const uint32_t*)(qb + (size_t)r1 * CCH + c + 8);
        }
    }

    float o[8][4];
    #pragma unroll
    for (int ht = 0; ht < 8; ht++)
        #pragma unroll
        for (int e = 0; e < 4; e++) o[ht][e] = 0.f;
    float l0 = 0.f, l1 = 0.f;

    #pragma unroll 1
    for (int jt = 0; jt < 32; jt++) {
        const int slot = jt % AT_NST;
        int rem = 31 - jt;
        if (rem >= 2)      asm volatile("cp.async.wait_group 2;");
        else if (rem == 1) asm volatile("cp.async.wait_group 1;");
        else               asm volatile("cp.async.wait_group 0;");
        __syncthreads();
        if (jt + 3 < 32) issue(jt + 3);

        uint32_t kaddr = sbase + slot * AT_STW * 4 + ldmoff;
        uint32_t vaddr = kaddr + 2304 * 4;

        float s[8][4];
        #pragma unroll
        for (int nt = 0; nt < 8; nt++)
            #pragma unroll
            for (int e = 0; e < 4; e++) s[nt][e] = 0.f;
        #pragma unroll
        for (int ks = 0; ks < 4; ks++) {
            uint32_t bf[8][2];
            #pragma unroll
            for (int p = 0; p < 4; p++)
                ldm_x4(bf[2 * p][0], bf[2 * p][1], bf[2 * p + 1][0], bf[2 * p + 1][1],
                       kaddr + p * (16 * 144) + ks * 32);
            #pragma unroll
            for (int nt = 0; nt < 8; nt++)
                mma_f16_b(s[nt], qa[ks], bf[nt][0], bf[nt][1]);
        }

        #pragma unroll
        for (int nt = 0; nt < 8; nt++) {
            int c0 = nt * 8 + 2 * gc;
            bool ok0 = s_mask[slot][c0] != 0;
            bool ok1 = s_mask[slot][c0 + 1] != 0;
            s[nt][0] = ok0 ? exp_small(s[nt][0]) : 0.f;
            s[nt][1] = ok1 ? exp_small(s[nt][1]) : 0.f;
            s[nt][2] = ok0 ? exp_small(s[nt][2]) : 0.f;
            s[nt][3] = ok1 ? exp_small(s[nt][3]) : 0.f;
            l0 += s[nt][0] + s[nt][1];
            l1 += s[nt][2] + s[nt][3];
        }

        #pragma unroll
        for (int ks = 0; ks < 4; ks++) {
            uint32_t aF[4];
            aF[0] = pack2f16(s[2 * ks][0],     s[2 * ks][1]);
            aF[1] = pack2f16(s[2 * ks][2],     s[2 * ks][3]);
            aF[2] = pack2f16(s[2 * ks + 1][0], s[2 * ks + 1][1]);
            aF[3] = pack2f16(s[2 * ks + 1][2], s[2 * ks + 1][3]);
            uint32_t vf[8][2];
            #pragma unroll
            for (int p = 0; p < 4; p++)
                ldm_x4(vf[2 * p][0], vf[2 * p][1], vf[2 * p + 1][0], vf[2 * p + 1][1],
                       vaddr + p * (16 * 144) + ks * 32);
            #pragma unroll
            for (int ht = 0; ht < 8; ht++)
                mma_f16_b(o[ht], aF, vf[ht][0], vf[ht][1]);
        }
    }

    l0 += __shfl_xor_sync(0xffffffffu, l0, 1);
    l0 += __shfl_xor_sync(0xffffffffu, l0, 2);
    l1 += __shfl_xor_sync(0xffffffffu, l1, 1);
    l1 += __shfl_xor_sync(0xffffffffu, l1, 2);
    {
        float inv0 = 1.f / l0, inv1 = 1.f / l1;
        int r0 = w * 16 + gr, r1 = r0 + 8;
        __half* Oh = AOh + ((size_t)(bb * SEQ + qt * 128)) * CCH + h * HDD;
        #pragma unroll
        for (int ht = 0; ht < 8; ht++) {
            int c = ht * 8 + 2 * gc;
            *(uint32_t*)(Oh + (size_t)r0 * CCH + c) = pack2f16(o[ht][0] * inv0, o[ht][1] * inv0);
            *(uint32_t*)(Oh + (size_t)r1 * CCH + c) = pack2f16(o[ht][2] * inv1, o[ht][3] * inv1);
        }
    }
}

// ---------------- host launcher ---------------------------------------------------
extern "C" void kernel_launch(void* const* d_in, const int* in_sizes, int n_in,
                              void* d_out, int out_size)
{
    const float* x    = (const float*)d_in[0];
    const int*   mask = (const int*)d_in[1];
    const float* wq   = (const float*)d_in[2];
    const float* bq   = (const float*)d_in[3];
    const float* wk   = (const float*)d_in[4];
    const float* bk   = (const float*)d_in[5];
    const float* wv   = (const float*)d_in[6];
    const float* bv   = (const float*)d_in[7];
    const float* qdww = (const float*)d_in[8];
    const float* qdwb = (const float*)d_in[9];
    const float* qpww = (const float*)d_in[10];
    const float* qpwb = (const float*)d_in[11];
    const float* kdww = (const float*)d_in[12];
    const float* kdwb = (const float*)d_in[13];
    const float* kpww = (const float*)d_in[14];
    const float* kpwb = (const float*)d_in[15];
    const float* vdww = (const float*)d_in[16];
    const float* vdwb = (const float*)d_in[17];
    const float* vpww = (const float*)d_in[18];
    const float* vpwb = (const float*)d_in[19];
    const float* wo   = (const float*)d_in[20];
    const float* bo   = (const float*)d_in[21];
    float* out = (float*)d_out;

    __half *xh, *w16, *q16, *k16, *v16, *qc16, *kc16, *vc16;
    __half *qpw, *kpw, *vpw, *qn, *kn, *vt, *aoh;
    float* dwt;
    cudaGetSymbolAddress((void**)&xh,  g_xh);
    cudaGetSymbolAddress((void**)&w16, g_w16);
    cudaGetSymbolAddress((void**)&dwt, g_dwt);
    cudaGetSymbolAddress((void**)&q16, g_q16);
    cudaGetSymbolAddress((void**)&k16, g_k16);
    cudaGetSymbolAddress((void**)&v16, g_v16);
    cudaGetSymbolAddress((void**)&qc16, g_qc16);
    cudaGetSymbolAddress((void**)&kc16, g_kc16);
    cudaGetSymbolAddress((void**)&vc16, g_vc16);
    cudaGetSymbolAddress((void**)&qpw, g_qpw);
    cudaGetSymbolAddress((void**)&kpw, g_kpw);
    cudaGetSymbolAddress((void**)&vpw, g_vpw);
    cudaGetSymbolAddress((void**)&qn,  g_qn);
    cudaGetSymbolAddress((void**)&kn,  g_kn);
    cudaGetSymbolAddress((void**)&vt,  g_vt);
    cudaGetSymbolAddress((void**)&aoh, g_aoh);

    __half* wqh  = w16 + 0 * (size_t)DIMM * CCH;
    __half* wkh  = w16 + 1 * (size_t)DIMM * CCH;
    __half* wvh  = w16 + 2 * (size_t)DIMM * CCH;
    __half* qpwh = w16 + 3 * (size_t)DIMM * CCH;
    __half* kpwh = w16 + 4 * (size_t)DIMM * CCH;
    __half* vpwh = w16 + 5 * (size_t)DIMM * CCH;
    __half* woh  = w16 + 6 * (size_t)DIMM * CCH;

    cudaFuncSetAttribute(gemm_h_k<true>,  cudaFuncAttributeMaxDynamicSharedMemorySize, G_SMEM);
    cudaFuncSetAttribute(gemm_h_k<false>, cudaFuncAttributeMaxDynamicSharedMemorySize, G_SMEM);
    cudaFuncSetAttribute(attn_mma_k, cudaFuncAttributeMaxDynamicSharedMemorySize, AT_SMEM);

    // 0) merged prep: weights + dw transpose + x fp16, one launch
    WC wc;
    wc.s[0] = wq;  wc.d[0] = wqh;
    wc.s[1] = wk;  wc.d[1] = wkh;
    wc.s[2] = wv;  wc.d[2] = wvh;
    wc.s[3] = qpww; wc.d[3] = qpwh;
    wc.s[4] = kpww; wc.d[4] = kpwh;
    wc.s[5] = vpww; wc.d[5] = vpwh;
    wc.s[6] = wo;  wc.d[6] = woh;
    wc.dw[0] = qdww; wc.dw[1] = kdww; wc.dw[2] = vdww;
    wc.dwt = dwt;
    wc.x = (const float2*)x; wc.xh = (uint32_t*)xh;
    prep_k<<<dim3(2048, 12), 256>>>(wc);

    dim3 grid_3(8, 64, 3), grid_1(8, 64, 1);

    // 1) QKV projection + SiLU (fused; all single-product fp16)
    gemm_h_k<true><<<grid_3, 256, G_SMEM>>>(
        GH{xh, wqh, bq, q16, 1},
        GH{xh, wkh, bk, k16, 1},
        GH{xh, wvh, bv, v16, 1});

    // 2) depthwise conv (fused q,k,v; vectorized fp16)
    dwconv_all_k<<<dim3(2048, 3), 256>>>(
        (const uint4*)q16, (const uint4*)k16, (const uint4*)v16,
        dwt, qdwb, kdwb, vdwb,
        (uint4*)qc16, (uint4*)kc16, (uint4*)vc16);

    // 3) pointwise conv (fused)
    gemm_h_k<false><<<grid_3, 256, G_SMEM>>>(
        GH{qc16, qpwh, qpwb, qpw, 1},
        GH{kc16, kpwh, kpwb, kpw, 1},
        GH{vc16, vpwh, vpwb, vpw, 1});

    // 4) merged l2norm (q scaled 0.125) + v transpose
    l2vt_k<<<dim3(8192, 3), 256>>>((const __half2*)qpw, (const __half2*)kpw,
                                   (__half2*)qn, (__half2*)kn, vpw, vt);

    // 5) flash attention -> fp16
    attn_mma_k<<<dim3(SEQ / 128, NHH, BSZ), 256, AT_SMEM>>>(qn, kn, vt, mask, aoh);

    // 6) output projection -> d_out (fp32)
    gemm_h_k<false><<<grid_1, 256, G_SMEM>>>(
        GH{aoh, woh, bo, out, 0},
        GH{aoh, woh, bo, out, 0},
        GH{aoh, woh, bo, out, 0});
}

// round 17
// speedup vs baseline: 1.2454x; 1.0323x over previous
#include <cuda_runtime.h>
#include <cuda_fp16.h>
#include <stdint.h>

#define BSZ 2
#define SEQ 2048
#define DIMM 1024
#define CCH 1024
#define NHH 16
#define HDD 64
#define MROWS (BSZ*SEQ)   // 4096

// ---------------- fp16 scratch (device globals) ----------------------------------
__device__ __half g_xh [MROWS*DIMM];
__device__ __half g_w16[7][DIMM*CCH];          // wq,wk,wv,qpw,kpw,vpw,wo
__device__ float  g_dwt[3*3*CCH];              // transposed dw weights [qkv][tap][C]
__device__ __half g_q16[MROWS*CCH],  g_k16[MROWS*CCH], g_v16[MROWS*CCH];
__device__ __half g_qc16[MROWS*CCH], g_kc16[MROWS*CCH], g_vc16[MROWS*CCH];
__device__ __half g_qpw[MROWS*CCH],  g_kpw[MROWS*CCH],  g_vpw[MROWS*CCH];
__device__ __half g_qn[MROWS*CCH],   g_kn[MROWS*CCH],   g_vt[MROWS*CCH];
__device__ __half g_aoh[MROWS*CCH];

// ================= helpers =======================================================
__device__ __forceinline__ uint32_t smem_u32(const void* p) {
    uint32_t a;
    asm("{ .reg .u64 t; cvta.to.shared.u64 t, %1; cvt.u32.u64 %0, t; }" : "=r"(a) : "l"(p));
    return a;
}
__device__ __forceinline__ uint32_t pack2f16(float x, float y) {
    __half2 t = __floats2half2_rn(x, y);
    return *reinterpret_cast<uint32_t*>(&t);
}
__device__ __forceinline__ void mma_f16(float* d, const uint32_t* a, const uint32_t* b) {
    asm volatile(
        "mma.sync.aligned.m16n8k16.row.col.f32.f16.f16.f32 "
        "{%0,%1,%2,%3}, {%4,%5,%6,%7}, {%8,%9}, {%0,%1,%2,%3};"
        : "+f"(d[0]), "+f"(d[1]), "+f"(d[2]), "+f"(d[3])
        : "r"(a[0]), "r"(a[1]), "r"(a[2]), "r"(a[3]), "r"(b[0]), "r"(b[1]));
}
__device__ __forceinline__ void mma_f16_b(float* d, const uint32_t* a, uint32_t b0, uint32_t b1) {
    asm volatile(
        "mma.sync.aligned.m16n8k16.row.col.f32.f16.f16.f32 "
        "{%0,%1,%2,%3}, {%4,%5,%6,%7}, {%8,%9}, {%0,%1,%2,%3};"
        : "+f"(d[0]), "+f"(d[1]), "+f"(d[2]), "+f"(d[3])
        : "r"(a[0]), "r"(a[1]), "r"(a[2]), "r"(a[3]), "r"(b0), "r"(b1));
}
__device__ __forceinline__ void ldm_x4(uint32_t& r0, uint32_t& r1, uint32_t& r2, uint32_t& r3,
                                       uint32_t addr) {
    asm volatile("ldmatrix.sync.aligned.m8n8.x4.shared.b16 {%0,%1,%2,%3}, [%4];"
                 : "=r"(r0), "=r"(r1), "=r"(r2), "=r"(r3) : "r"(addr));
}
__device__ __forceinline__ float exp_small(float x) {   // |x| <= 0.125, rel err ~3e-8
    return 1.f + x * (1.f + x * (0.5f + x * (0.166666667f + x * 0.0416666667f)));
}

// ================= merged prep kernel ============================================
struct WC { const float* s[7]; __half* d[7]; const float* dw[3]; float* dwt;
            const float2* x; uint32_t* xh; };
__global__ void prep_k(WC wc)
{
    int z = blockIdx.y;
    int i = blockIdx.x * 256 + threadIdx.x;
    if (z < 7) {
        const float2* s = (const float2*)wc.s[z];
        __half2* d = (__half2*)wc.d[z];
        float2 v = s[i];
        d[i] = __floats2half2_rn(v.x, v.y);
    } else if (z == 7) {
        if (i < 3 * 3 * CCH) {
            int plane = i / (3 * CCH);
            int r = i % (3 * CCH);
            int tap = r >> 10, c = r & (CCH - 1);
            wc.dwt[plane * 3 * CCH + tap * CCH + c] = wc.dw[plane][c * 3 + tap];
        }
    } else {
        int idx = (z - 8) * 524288 + i;
        float2 v = wc.x[idx];
        wc.xh[idx] = pack2f16(v.x, v.y);
    }
}

// ================= fp16 GEMM: CTA 128x128, warp tile 64x32, occ 2 ================
// C[m,n] = sum_k A[m,k]*W[n,k] + bias[n]; M=4096, N=K=1024. fp16 in.
// omode runtime: 0=f32 out, 1=f16 out. KC=32, 256 thr (2x4 warps), 3 stages.
struct GH { const __half* A; const __half* W; const float* bias; void* C; int omode; };

#define PL_A 10240                   // A plane: 128 rows x 80B
#define PL_B 10240                   // B plane: 128 rows x 80B
#define G_STB (PL_A + PL_B)          // 20480
#define G_NST 3
#define G_SMEM (G_NST*G_STB)         // 61440

template<bool SILU>
__global__ void __launch_bounds__(256, 2)
gemm_h_k(GH g0, GH g1, GH g2)
{
    GH g = (blockIdx.z == 0) ? g0 : ((blockIdx.z == 1) ? g1 : g2);
    extern __shared__ uint32_t smw[];
    const uint32_t sb = smem_u32(smw);

    const int tid = threadIdx.x, lane = tid & 31, wid = tid >> 5;
    const int wm = wid & 1, wn = wid >> 1;       // 2x4 warp grid; warp tile 64x32
    const int gr = lane >> 2, gc = lane & 3;
    const int m0 = blockIdx.y * 128, n0 = blockIdx.x * 128;

    // cp.async geometry: A 128 rows x 4 chunks = 512; B same; 2+2 chunks/thread
    const int c0r = tid >> 2, c0c = tid & 3;         // chunk tid
    const int c1r = (tid + 256) >> 2, c1c = (tid + 256) & 3;
    const __half* paA0 = g.A + (size_t)(m0 + c0r) * DIMM + c0c * 8;
    const __half* paA1 = g.A + (size_t)(m0 + c1r) * DIMM + c1c * 8;
    const __half* pwB0 = g.W + (size_t)(n0 + c0r) * DIMM + c0c * 8;
    const __half* pwB1 = g.W + (size_t)(n0 + c1r) * DIMM + c1c * 8;
    const uint32_t dA0 = sb + c0r * 80 + c0c * 16;
    const uint32_t dA1 = sb + c1r * 80 + c1c * 16;
    const uint32_t dB0 = sb + PL_A + c0r * 80 + c0c * 16;
    const uint32_t dB1 = sb + PL_A + c1r * 80 + c1c * 16;

    const uint32_t aoff = (uint32_t)(wm * 64 + (lane & 15)) * 80 + ((lane >> 4) << 4);
    const uint32_t boff = PL_A +
        (uint32_t)(wn * 32 + ((lane >> 4) << 3) + (lane & 7)) * 80 + (((lane >> 3) & 1) << 4);

    auto issue = [&](int i) {
        int kk = i * 32;
        uint32_t st = (i % G_NST) * G_STB;
        asm volatile("cp.async.cg.shared.global [%0], [%1], 16;" :: "r"(dA0 + st), "l"(paA0 + kk));
        asm volatile("cp.async.cg.shared.global [%0], [%1], 16;" :: "r"(dA1 + st), "l"(paA1 + kk));
        asm volatile("cp.async.cg.shared.global [%0], [%1], 16;" :: "r"(dB0 + st), "l"(pwB0 + kk));
        asm volatile("cp.async.cg.shared.global [%0], [%1], 16;" :: "r"(dB1 + st), "l"(pwB1 + kk));
        asm volatile("cp.async.commit_group;");
    };

    float acc[4][4][4];
    #pragma unroll
    for (int mi = 0; mi < 4; mi++)
        #pragma unroll
        for (int ni = 0; ni < 4; ni++)
            #pragma unroll
            for (int e = 0; e < 4; e++) acc[mi][ni][e] = 0.f;

    issue(0); issue(1);

    #pragma unroll 1
    for (int i = 0; i < 32; i++) {
        if (31 - i >= 1) asm volatile("cp.async.wait_group 1;");
        else             asm volatile("cp.async.wait_group 0;");
        __syncthreads();
        if (i + 2 < 32) issue(i + 2);

        uint32_t stb = sb + (i % G_NST) * G_STB;
        #pragma unroll
        for (int ki = 0; ki < 2; ki++) {
            uint32_t koff = ki * 32;
            uint32_t ah[4][4], bf[4][2];
            ldm_x4(ah[0][0], ah[0][1], ah[0][2], ah[0][3], stb + aoff + koff);
            ldm_x4(ah[1][0], ah[1][1], ah[1][2], ah[1][3], stb + aoff + 16 * 80 + koff);
            ldm_x4(ah[2][0], ah[2][1], ah[2][2], ah[2][3], stb + aoff + 32 * 80 + koff);
            ldm_x4(ah[3][0], ah[3][1], ah[3][2], ah[3][3], stb + aoff + 48 * 80 + koff);
            ldm_x4(bf[0][0], bf[0][1], bf[1][0], bf[1][1], stb + boff + koff);
            ldm_x4(bf[2][0], bf[2][1], bf[3][0], bf[3][1], stb + boff + 16 * 80 + koff);
            #pragma unroll
            for (int ni = 0; ni < 4; ni++)
                #pragma unroll
                for (int mi = 0; mi < 4; mi++)
                    mma_f16(acc[mi][ni], ah[mi], bf[ni]);
        }
    }

    const int omode = g.omode;
    #pragma unroll
    for (int ni = 0; ni < 4; ni++) {
        int cg = n0 + wn * 32 + ni * 8 + 2 * gc;
        float b0 = g.bias[cg], b1 = g.bias[cg + 1];
        #pragma unroll
        for (int mi = 0; mi < 4; mi++) {
            int r = m0 + wm * 64 + mi * 16 + gr;
            float v0 = acc[mi][ni][0] + b0;
            float v1 = acc[mi][ni][1] + b1;
            float v2 = acc[mi][ni][2] + b0;
            float v3 = acc[mi][ni][3] + b1;
            if (SILU) {
                v0 = v0 / (1.f + __expf(-v0));
                v1 = v1 / (1.f + __expf(-v1));
                v2 = v2 / (1.f + __expf(-v2));
                v3 = v3 / (1.f + __expf(-v3));
            }
            if (omode == 0) {
                float* C = (float*)g.C;
                *(float2*)(C + (size_t)r * CCH + cg)       = make_float2(v0, v1);
                *(float2*)(C + (size_t)(r + 8) * CCH + cg) = make_float2(v2, v3);
            } else {
                __half* C = (__half*)g.C;
                *(uint32_t*)(C + (size_t)r * CCH + cg)       = pack2f16(v0, v1);
                *(uint32_t*)(C + (size_t)(r + 8) * CCH + cg) = pack2f16(v2, v3);
            }
        }
    }
}

// ---------------- fused depthwise conv k=3, vectorized (8 ch/thread), fp16 -------
__global__ void __launch_bounds__(256) dwconv_all_k(
    const uint4* q, const uint4* k, const uint4* v,
    const float* dwt, const float* bq, const float* bk, const float* bv,
    uint4* oq, uint4* ok, uint4* ov)
{
    const int z = blockIdx.y;
    const int i4 = blockIdx.x * 256 + threadIdx.x;   // < 524288
    const int c8 = i4 & 127, m = i4 >> 7, s = m & (SEQ - 1);
    const int c0 = c8 * 8;

    const float* wt = dwt + z * 3 * CCH;
    const float* bb = (z == 0) ? bq : ((z == 1) ? bk : bv);
    const uint4* in = (z == 0) ? q : ((z == 1) ? k : v);
    uint4* out      = (z == 0) ? oq : ((z == 1) ? ok : ov);

    float w0[8], w1[8], w2[8], bvv[8];
    *(float4*)&w0[0] = *(const float4*)(wt + c0);
    *(float4*)&w0[4] = *(const float4*)(wt + c0 + 4);
    *(float4*)&w1[0] = *(const float4*)(wt + CCH + c0);
    *(float4*)&w1[4] = *(const float4*)(wt + CCH + c0 + 4);
    *(float4*)&w2[0] = *(const float4*)(wt + 2 * CCH + c0);
    *(float4*)&w2[4] = *(const float4*)(wt + 2 * CCH + c0 + 4);
    *(float4*)&bvv[0] = *(const float4*)(bb + c0);
    *(float4*)&bvv[4] = *(const float4*)(bb + c0 + 4);

    const uint4 zero4 = make_uint4(0, 0, 0, 0);
    uint4 xc = in[i4];
    uint4 xm = (s > 0) ? in[i4 - 128] : zero4;
    uint4 xp = (s < SEQ - 1) ? in[i4 + 128] : zero4;

    float xc_[8], xm_[8], xp_[8];
    #pragma unroll
    for (int j = 0; j < 4; j++) {
        float2 a = __half22float2(((const __half2*)&xc)[j]); xc_[2*j] = a.x; xc_[2*j+1] = a.y;
        float2 b = __half22float2(((const __half2*)&xm)[j]); xm_[2*j] = b.x; xm_[2*j+1] = b.y;
        float2 c = __half22float2(((const __half2*)&xp)[j]); xp_[2*j] = c.x; xp_[2*j+1] = c.y;
    }
    uint4 o4;
    #pragma unroll
    for (int j = 0; j < 4; j++) {
        float r0 = xm_[2*j]   * w0[2*j]   + xc_[2*j]   * w1[2*j]   + xp_[2*j]   * w2[2*j]   + bvv[2*j];
        float r1 = xm_[2*j+1] * w0[2*j+1] + xc_[2*j+1] * w1[2*j+1] + xp_[2*j+1] * w2[2*j+1] + bvv[2*j+1];
        ((uint32_t*)&o4)[j] = pack2f16(r0, r1);
    }
    out[i4] = o4;
}

// ---------------- merged l2norm (z=0:q, z=1:k) + vtrans (z=2) --------------------
__global__ void l2vt_k(const __half2* q, const __half2* k, __half2* qn, __half2* kn,
                       const __half* v, __half* vt)
{
    int z = blockIdx.y;
    if (z < 2) {
        const __half2* src = z ? k : q;
        __half2* dst = z ? kn : qn;
        float sc = z ? 1.0f : 0.125f;
        int warp = threadIdx.x >> 5, lane = threadIdx.x & 31;
        size_t g = (size_t)blockIdx.x * 8 + warp;
        float2 x = __half22float2(src[g * 32 + lane]);
        float ss = x.x * x.x + x.y * x.y;
        #pragma unroll
        for (int o = 16; o; o >>= 1) ss += __shfl_xor_sync(0xffffffffu, ss, o);
        float inv = sc / fmaxf(sqrtf(ss), 1e-12f);
        dst[g * 32 + lane] = __floats2half2_rn(x.x * inv, x.y * inv);
    } else {
        int bx = blockIdx.x;
        if (bx >= 4096) return;
        __shared__ float t[32][33];
        int cB = bx & 31, sB = (bx >> 5) & 63, b = bx >> 11;
        int tx = threadIdx.x & 31, ty = threadIdx.x >> 5;   // 32x8
        int s0 = sB * 32, c0 = cB * 32;
        #pragma unroll
        for (int j = 0; j < 4; j++)
            t[ty + 8 * j][tx] = __half2float(v[(size_t)(b * SEQ + s0 + ty + 8 * j) * CCH + c0 + tx]);
        __syncthreads();
        #pragma unroll
        for (int j = 0; j < 4; j++)
            vt[(size_t)(b * CCH + c0 + ty + 8 * j) * SEQ + s0 + tx] = __float2half(t[tx][ty + 8 * j]);
    }
}

// ================= flash attention: cp.async + ldmatrix fp16, 4-stage, occ 2 =====
#define AT_STW 4608
#define AT_NST 4
#define AT_SMEM (AT_NST*AT_STW*4)    // 73728 B

__global__ void __launch_bounds__(256, 2) attn_mma_k(const __half* __restrict__ Qh,
                                                     const __half* __restrict__ Kh,
                                                     const __half* __restrict__ Vt,
                                                     const int* __restrict__ mask,
                                                     __half* __restrict__ AOh)
{
    const int qt = blockIdx.x, h = blockIdx.y, bb = blockIdx.z;
    extern __shared__ uint32_t asw[];
    __shared__ int s_mask[AT_NST][64];

    const int tid = threadIdx.x, lane = tid & 31, w = tid >> 5;
    const int gr = lane >> 2, gc = lane & 3;
    const uint32_t sbase = smem_u32(asw);

    const __half* kb = Kh + ((size_t)bb * SEQ) * CCH + h * HDD;
    const __half* vb = Vt + ((size_t)(bb * NHH + h)) * HDD * SEQ;

    const uint32_t ldmoff =
        (uint32_t)(((lane >> 4) << 3) + (lane & 7)) * 144 + (((lane >> 3) & 1) << 4);

    auto issue = [&](int jt) {
        int slot = jt % AT_NST;
        uint32_t kdst = sbase + slot * AT_STW * 4;
        uint32_t vdst = kdst + 2304 * 4;
        #pragma unroll
        for (int j = 0; j < 2; j++) {
            int c = tid + 256 * j;
            int row = c >> 3, ch = c & 7;
            uint32_t d = kdst + (row * 36 + ch * 4) * 4;
            const __half* s = kb + (size_t)(jt * 64 + row) * CCH + ch * 8;
            asm volatile("cp.async.cg.shared.global [%0], [%1], 16;" :: "r"(d), "l"(s));
        }
        #pragma unroll
        for (int j = 0; j < 2; j++) {
            int c = tid + 256 * j;
            int row = c >> 3, ch = c & 7;
            uint32_t d = vdst + (row * 36 + ch * 4) * 4;
            const __half* s = vb + (size_t)row * SEQ + jt * 64 + ch * 8;
            asm volatile("cp.async.cg.shared.global [%0], [%1], 16;" :: "r"(d), "l"(s));
        }
        if (tid < 16) {
            uint32_t d = smem_u32(&s_mask[slot][0]) + tid * 16;
            const int* s = mask + bb * SEQ + jt * 64 + tid * 4;
            asm volatile("cp.async.cg.shared.global [%0], [%1], 16;" :: "r"(d), "l"(s));
        }
        asm volatile("cp.async.commit_group;");
    };

    issue(0);
    issue(1);
    issue(2);

    uint32_t qa[4][4];
    {
        const __half* qb = Qh + ((size_t)(bb * SEQ + qt * 128)) * CCH + h * HDD;
        int r0 = w * 16 + gr, r1 = r0 + 8;
        #pragma unroll
        for (int ks = 0; ks < 4; ks++) {
            int c = ks * 16 + 2 * gc;
            qa[ks][0] = *(const uint32_t*)(qb + (size_t)r0 * CCH + c);
            qa[ks][1] = *(const uint32_t*)(qb + (size_t)r1 * CCH + c);
            qa[ks][2] = *(const uint32_t*)(qb + (size_t)r0 * CCH + c + 8);
            qa[ks][3] = *(const uint32_t*)(qb + (size_t)r1 * CCH + c + 8);
        }
    }

    float o[8][4];
    #pragma unroll
    for (int ht = 0; ht < 8; ht++)
        #pragma unroll
        for (int e = 0; e < 4; e++) o[ht][e] = 0.f;
    float l0 = 0.f, l1 = 0.f;

    #pragma unroll 1
    for (int jt = 0; jt < 32; jt++) {
        const int slot = jt % AT_NST;
        int rem = 31 - jt;
        if (rem >= 2)      asm volatile("cp.async.wait_group 2;");
        else if (rem == 1) asm volatile("cp.async.wait_group 1;");
        else               asm volatile("cp.async.wait_group 0;");
        __syncthreads();
        if (jt + 3 < 32) issue(jt + 3);

        uint32_t kaddr = sbase + slot * AT_STW * 4 + ldmoff;
        uint32_t vaddr = kaddr + 2304 * 4;

        float s[8][4];
        #pragma unroll
        for (int nt = 0; nt < 8; nt++)
            #pragma unroll
            for (int e = 0; e < 4; e++) s[nt][e] = 0.f;
        #pragma unroll
        for (int ks = 0; ks < 4; ks++) {
            uint32_t bf[8][2];
            #pragma unroll
            for (int p = 0; p < 4; p++)
                ldm_x4(bf[2 * p][0], bf[2 * p][1], bf[2 * p + 1][0], bf[2 * p + 1][1],
                       kaddr + p * (16 * 144) + ks * 32);
            #pragma unroll
            for (int nt = 0; nt < 8; nt++)
                mma_f16_b(s[nt], qa[ks], bf[nt][0], bf[nt][1]);
        }

        #pragma unroll
        for (int nt = 0; nt < 8; nt++) {
            int c0 = nt * 8 + 2 * gc;
            bool ok0 = s_mask[slot][c0] != 0;
            bool ok1 = s_mask[slot][c0 + 1] != 0;
            s[nt][0] = ok0 ? exp_small(s[nt][0]) : 0.f;
            s[nt][1] = ok1 ? exp_small(s[nt][1]) : 0.f;
            s[nt][2] = ok0 ? exp_small(s[nt][2]) : 0.f;
            s[nt][3] = ok1 ? exp_small(s[nt][3]) : 0.f;
            l0 += s[nt][0] + s[nt][1];
            l1 += s[nt][2] + s[nt][3];
        }

        #pragma unroll
        for (int ks = 0; ks < 4; ks++) {
            uint32_t aF[4];
            aF[0] = pack2f16(s[2 * ks][0],     s[2 * ks][1]);
            aF[1] = pack2f16(s[2 * ks][2],     s[2 * ks][3]);
            aF[2] = pack2f16(s[2 * ks + 1][0], s[2 * ks + 1][1]);
            aF[3] = pack2f16(s[2 * ks + 1][2], s[2 * ks + 1][3]);
            uint32_t vf[8][2];
            #pragma unroll
            for (int p = 0; p < 4; p++)
                ldm_x4(vf[2 * p][0], vf[2 * p][1], vf[2 * p + 1][0], vf[2 * p + 1][1],
                       vaddr + p * (16 * 144) + ks * 32);
            #pragma unroll
            for (int ht = 0; ht < 8; ht++)
                mma_f16_b(o[ht], aF, vf[ht][0], vf[ht][1]);
        }
    }

    l0 += __shfl_xor_sync(0xffffffffu, l0, 1);
    l0 += __shfl_xor_sync(0xffffffffu, l0, 2);
    l1 += __shfl_xor_sync(0xffffffffu, l1, 1);
    l1 += __shfl_xor_sync(0xffffffffu, l1, 2);
    {
        float inv0 = 1.f / l0, inv1 = 1.f / l1;
        int r0 = w * 16 + gr, r1 = r0 + 8;
        __half* Oh = AOh + ((size_t)(bb * SEQ + qt * 128)) * CCH + h * HDD;
        #pragma unroll
        for (int ht = 0; ht < 8; ht++) {
            int c = ht * 8 + 2 * gc;
            *(uint32_t*)(Oh + (size_t)r0 * CCH + c) = pack2f16(o[ht][0] * inv0, o[ht][1] * inv0);
            *(uint32_t*)(Oh + (size_t)r1 * CCH + c) = pack2f16(o[ht][2] * inv1, o[ht][3] * inv1);
        }
    }
}

// ---------------- host launcher ---------------------------------------------------
extern "C" void kernel_launch(void* const* d_in, const int* in_sizes, int n_in,
                              void* d_out, int out_size)
{
    const float* x    = (const float*)d_in[0];
    const int*   mask = (const int*)d_in[1];
    const float* wq   = (const float*)d_in[2];
    const float* bq   = (const float*)d_in[3];
    const float* wk   = (const float*)d_in[4];
    const float* bk   = (const float*)d_in[5];
    const float* wv   = (const float*)d_in[6];
    const float* bv   = (const float*)d_in[7];
    const float* qdww = (const float*)d_in[8];
    const float* qdwb = (const float*)d_in[9];
    const float* qpww = (const float*)d_in[10];
    const float* qpwb = (const float*)d_in[11];
    const float* kdww = (const float*)d_in[12];
    const float* kdwb = (const float*)d_in[13];
    const float* kpww = (const float*)d_in[14];
    const float* kpwb = (const float*)d_in[15];
    const float* vdww = (const float*)d_in[16];
    const float* vdwb = (const float*)d_in[17];
    const float* vpww = (const float*)d_in[18];
    const float* vpwb = (const float*)d_in[19];
    const float* wo   = (const float*)d_in[20];
    const float* bo   = (const float*)d_in[21];
    float* out = (float*)d_out;

    __half *xh, *w16, *q16, *k16, *v16, *qc16, *kc16, *vc16;
    __half *qpw, *kpw, *vpw, *qn, *kn, *vt, *aoh;
    float* dwt;
    cudaGetSymbolAddress((void**)&xh,  g_xh);
    cudaGetSymbolAddress((void**)&w16, g_w16);
    cudaGetSymbolAddress((void**)&dwt, g_dwt);
    cudaGetSymbolAddress((void**)&q16, g_q16);
    cudaGetSymbolAddress((void**)&k16, g_k16);
    cudaGetSymbolAddress((void**)&v16, g_v16);
    cudaGetSymbolAddress((void**)&qc16, g_qc16);
    cudaGetSymbolAddress((void**)&kc16, g_kc16);
    cudaGetSymbolAddress((void**)&vc16, g_vc16);
    cudaGetSymbolAddress((void**)&qpw, g_qpw);
    cudaGetSymbolAddress((void**)&kpw, g_kpw);
    cudaGetSymbolAddress((void**)&vpw, g_vpw);
    cudaGetSymbolAddress((void**)&qn,  g_qn);
    cudaGetSymbolAddress((void**)&kn,  g_kn);
    cudaGetSymbolAddress((void**)&vt,  g_vt);
    cudaGetSymbolAddress((void**)&aoh, g_aoh);

    __half* wqh  = w16 + 0 * (size_t)DIMM * CCH;
    __half* wkh  = w16 + 1 * (size_t)DIMM * CCH;
    __half* wvh  = w16 + 2 * (size_t)DIMM * CCH;
    __half* qpwh = w16 + 3 * (size_t)DIMM * CCH;
    __half* kpwh = w16 + 4 * (size_t)DIMM * CCH;
    __half* vpwh = w16 + 5 * (size_t)DIMM * CCH;
    __half* woh  = w16 + 6 * (size_t)DIMM * CCH;

    cudaFuncSetAttribute(gemm_h_k<true>,  cudaFuncAttributeMaxDynamicSharedMemorySize, G_SMEM);
    cudaFuncSetAttribute(gemm_h_k<false>, cudaFuncAttributeMaxDynamicSharedMemorySize, G_SMEM);
    cudaFuncSetAttribute(attn_mma_k, cudaFuncAttributeMaxDynamicSharedMemorySize, AT_SMEM);

    // 0) merged prep: weights + dw transpose + x fp16, one launch
    WC wc;
    wc.s[0] = wq;  wc.d[0] = wqh;
    wc.s[1] = wk;  wc.d[1] = wkh;
    wc.s[2] = wv;  wc.d[2] = wvh;
    wc.s[3] = qpww; wc.d[3] = qpwh;
    wc.s[4] = kpww; wc.d[4] = kpwh;
    wc.s[5] = vpww; wc.d[5] = vpwh;
    wc.s[6] = wo;  wc.d[6] = woh;
    wc.dw[0] = qdww; wc.dw[1] = kdww; wc.dw[2] = vdww;
    wc.dwt = dwt;
    wc.x = (const float2*)x; wc.xh = (uint32_t*)xh;
    prep_k<<<dim3(2048, 12), 256>>>(wc);

    dim3 grid_3(8, 32, 3), grid_1(8, 32, 1);

    // 1) QKV projection + SiLU (fused; single-product fp16, 128x128 CTA)
    gemm_h_k<true><<<grid_3, 256, G_SMEM>>>(
        GH{xh, wqh, bq, q16, 1},
        GH{xh, wkh, bk, k16, 1},
        GH{xh, wvh, bv, v16, 1});

    // 2) depthwise conv (fused q,k,v; vectorized fp16)
    dwconv_all_k<<<dim3(2048, 3), 256>>>(
        (const uint4*)q16, (const uint4*)k16, (const uint4*)v16,
        dwt, qdwb, kdwb, vdwb,
        (uint4*)qc16, (uint4*)kc16, (uint4*)vc16);

    // 3) pointwise conv (fused)
    gemm_h_k<false><<<grid_3, 256, G_SMEM>>>(
        GH{qc16, qpwh, qpwb, qpw, 1},
        GH{kc16, kpwh, kpwb, kpw, 1},
        GH{vc16, vpwh, vpwb, vpw, 1});

    // 4) merged l2norm (q scaled 0.125) + v transpose
    l2vt_k<<<dim3(8192, 3), 256>>>((const __half2*)qpw, (const __half2*)kpw,
                                   (__half2*)qn, (__half2*)kn, vpw, vt);

    // 5) flash attention -> fp16
    attn_mma_k<<<dim3(SEQ / 128, NHH, BSZ), 256, AT_SMEM>>>(qn, kn, vt, mask, aoh);

    // 6) output projection -> d_out (fp32)
    gemm_h_k<false><<<grid_1, 256, G_SMEM>>>(
        GH{aoh, woh, bo, out, 0},
        GH{aoh, woh, bo, out, 0},
        GH{aoh, woh, bo, out, 0});
}